// round 14
// baseline (speedup 1.0000x reference)
#include <cuda_runtime.h>
#include <cstdint>

constexpr int cB = 64, cN = 196, cD = 768, cH = 3072;
constexpr int cM = cB * cN;            // 12544
constexpr int BNDTOT = cB * cN * cD;   // 9633792
constexpr int HDTOT = cH * cD;         // 2359296

__device__ int g_maxbits[7];           // zero-init; atomicMax idempotent across graph replays

__device__ signed char g_X0[BNDTOT];
__device__ signed char g_X1t[BNDTOT];          // [B,D,N]
__device__ signed char g_X3[BNDTOT];
__device__ signed char g_X4[BNDTOT];
__device__ signed char g_X5[(long long)cM * cH];
__device__ signed char g_aw8[cN * cN];
__device__ int  g_ab32[cN];
__device__ signed char g_f1w8[HDTOT];
__device__ int  g_f1b[cH];
__device__ signed char g_f2w8[HDTOT];
__device__ int  g_f2b[cD];
__device__ int  g_g1wi[cD], g_n2wi[cD], g_b2i[cD], g_g2wi[cD];

__device__ __forceinline__ int clamp8(int v) { return max(-128, min(127, v)); }
__device__ __forceinline__ int rni(float f)  { return __float2int_rn(f); }
__device__ __forceinline__ float wsf_of(int slot) {
    return __fdiv_rn(__int_as_float(g_maxbits[slot]), 127.0f);
}

__device__ __forceinline__ uint32_t smem_u32(const void* p) {
    uint32_t a;
    asm("{ .reg .u64 t; cvta.to.shared.u64 t, %1; cvt.u32.u64 %0, t; }" : "=r"(a) : "l"(p));
    return a;
}

#define CP16(d, s) asm volatile("cp.async.cg.shared.global [%0], [%1], 16;" :: "r"(d), "l"(s))
#define CPCOMMIT() asm volatile("cp.async.commit_group;" ::: "memory")
#define CPWAIT(n)  asm volatile("cp.async.wait_group %0;" :: "n"(n) : "memory")

// ---------------- launch 1: maxabs reductions ----------------
__global__ void k_maxabs(const float* n1w, const float* aw, const float* g1,
                         const float* n2w, const float* f1, const float* f2, const float* g2) {
    int bid = blockIdx.x;
    const float* src; int slot, n, base;
    if (bid < 288)      { src = f1; slot = 4; n = HDTOT;   base = bid; }
    else if (bid < 576) { src = f2; slot = 5; n = HDTOT;   base = bid - 288; }
    else if (bid < 581) { src = aw; slot = 1; n = cN * cN; base = bid - 576; }
    else {
        base = 0; n = cD;
        int s = bid - 581;
        if (s == 0)      { src = n1w; slot = 0; }
        else if (s == 1) { src = g1;  slot = 2; }
        else if (s == 2) { src = n2w; slot = 3; }
        else             { src = g2;  slot = 6; }
    }
    int start = base * 8192;
    int end = min(n, start + 8192);
    float m = 0.f;
    for (int i = start + threadIdx.x; i < end; i += 256) m = fmaxf(m, fabsf(src[i]));
    #pragma unroll
    for (int o = 16; o; o >>= 1) m = fmaxf(m, __shfl_xor_sync(0xffffffffu, m, o));
    __shared__ float sm[8];
    if ((threadIdx.x & 31) == 0) sm[threadIdx.x >> 5] = m;
    __syncthreads();
    if (threadIdx.x == 0) {
        for (int i = 1; i < 8; i++) m = fmaxf(m, sm[i]);
        atomicMax(&g_maxbits[slot], __float_as_int(m));
    }
}

// ---------------- launch 2: fused quantw + input ----------------
constexpr int HD4 = HDTOT / 4;
constexpr int RESTQ = cN * cN + cN + cH + cD + 4 * cD;
constexpr int TOTQ = 2 * HD4 + RESTQ;
constexpr int QW_BLOCKS = (TOTQ + 255) / 256;
constexpr int IN_BLOCKS = 12 * 4 * cB;   // 3072

__global__ void k_qwin(const float* n1w, const float* n1b, const float* aw, const float* ab,
                       const float* g1, const float* n2w, const float* n2b,
                       const float* f1w, const float* f1b, const float* f2w, const float* f2b,
                       const float* g2, const float* __restrict__ x,
                       const float* __restrict__ sfs) {
    __shared__ signed char s[64][68];
    __shared__ int swv[64], sbv[64];
    if (blockIdx.x < QW_BLOCKS) {
        const float w1 = wsf_of(1), w2 = wsf_of(2), w3 = wsf_of(3);
        const float w4 = wsf_of(4), w5 = wsf_of(5), w6 = wsf_of(6);
        const float sf1 = sfs[1], sf3 = sfs[3], sf4 = sfs[4], sf5 = sfs[5];
        const float den_ab  = __fmul_rn(sf1, w1);
        const float den_b2  = __fmul_rn(sf3, w3);
        const float den_f1b = __fmul_rn(sf4, w4);
        const float den_f2b = __fmul_rn(sf5, w5);

        int idx = blockIdx.x * 256 + threadIdx.x;
        if (idx < HD4) {
            float4 v = reinterpret_cast<const float4*>(f1w)[idx];
            char4 o;
            o.x = (signed char)clamp8(rni(__fdiv_rn(v.x, w4)));
            o.y = (signed char)clamp8(rni(__fdiv_rn(v.y, w4)));
            o.z = (signed char)clamp8(rni(__fdiv_rn(v.z, w4)));
            o.w = (signed char)clamp8(rni(__fdiv_rn(v.w, w4)));
            reinterpret_cast<char4*>(g_f1w8)[idx] = o;
            return;
        }
        idx -= HD4;
        if (idx < HD4) {
            float4 v = reinterpret_cast<const float4*>(f2w)[idx];
            char4 o;
            o.x = (signed char)clamp8(rni(__fdiv_rn(v.x, w5)));
            o.y = (signed char)clamp8(rni(__fdiv_rn(v.y, w5)));
            o.z = (signed char)clamp8(rni(__fdiv_rn(v.z, w5)));
            o.w = (signed char)clamp8(rni(__fdiv_rn(v.w, w5)));
            reinterpret_cast<char4*>(g_f2w8)[idx] = o;
            return;
        }
        idx -= HD4;
        if (idx < cN * cN) { g_aw8[idx] = (signed char)clamp8(rni(__fdiv_rn(aw[idx], w1))); return; }
        idx -= cN * cN;
        if (idx < cN) { g_ab32[idx] = rni(__fdiv_rn(ab[idx], den_ab)); return; }
        idx -= cN;
        if (idx < cH) { g_f1b[idx] = rni(__fdiv_rn(f1b[idx], den_f1b)); return; }
        idx -= cH;
        if (idx < cD) { g_f2b[idx] = rni(__fdiv_rn(f2b[idx], den_f2b)); return; }
        idx -= cD;
        if (idx < cD) { g_g1wi[idx] = rni(__fdiv_rn(g1[idx],  w2)); return; }
        idx -= cD;
        if (idx < cD) { g_n2wi[idx] = rni(__fdiv_rn(n2w[idx], w3)); return; }
        idx -= cD;
        if (idx < cD) { g_b2i[idx]  = rni(__fdiv_rn(n2b[idx], den_b2)); return; }
        idx -= cD;
        if (idx < cD) { g_g2wi[idx] = rni(__fdiv_rn(g2[idx],  w6)); return; }
        return;
    }
    // ---- input branch ----
    const float w0 = wsf_of(0);
    const float s0 = sfs[0];
    const float den_b1 = __fmul_rn(s0, w0);
    const float r1 = __fdiv_rn(den_b1, sfs[1]);
    int v = blockIdx.x - QW_BLOCKS;
    const int dt = v % 12, nt = (v / 12) % 4, b = v / 48;
    const int n0 = nt * 64, d0 = dt * 64;
    if (threadIdx.x < 64) {
        swv[threadIdx.x] = rni(__fdiv_rn(n1w[d0 + threadIdx.x], w0));
        sbv[threadIdx.x] = rni(__fdiv_rn(n1b[d0 + threadIdx.x], den_b1));
    }
    __syncthreads();
    const float* xb = x + (size_t)b * cN * cD;
    signed char* x0b = g_X0 + (size_t)b * cN * cD;
    #pragma unroll
    for (int it = 0; it < 4; it++) {
        int e = threadIdx.x + it * 256;
        int nl = e >> 4, gl = e & 15;
        int n = n0 + nl, d = d0 + gl * 4;
        if (n < cN) {
            float4 xv = *(const float4*)&xb[n * cD + d];
            int4 wv = *(const int4*)&swv[gl * 4];
            int4 bv = *(const int4*)&sbv[gl * 4];
            int xa = rni(__fdiv_rn(xv.x, s0));
            int xbq = rni(__fdiv_rn(xv.y, s0));
            int xc = rni(__fdiv_rn(xv.z, s0));
            int xd = rni(__fdiv_rn(xv.w, s0));
            char4 c0;
            c0.x = (signed char)xa; c0.y = (signed char)xbq;
            c0.z = (signed char)xc; c0.w = (signed char)xd;
            *(char4*)&x0b[n * cD + d] = c0;
            s[nl][gl * 4 + 0] = (signed char)clamp8(rni(__fmul_rn((float)(xa  * wv.x + bv.x), r1)));
            s[nl][gl * 4 + 1] = (signed char)clamp8(rni(__fmul_rn((float)(xbq * wv.y + bv.y), r1)));
            s[nl][gl * 4 + 2] = (signed char)clamp8(rni(__fmul_rn((float)(xc  * wv.z + bv.z), r1)));
            s[nl][gl * 4 + 3] = (signed char)clamp8(rni(__fmul_rn((float)(xd  * wv.w + bv.w), r1)));
        }
    }
    __syncthreads();
    #pragma unroll
    for (int it = 0; it < 16; it++) {
        int e = threadIdx.x + it * 256;
        int dl = e >> 6, nl = e & 63;
        int n = n0 + nl;
        if (n < cN) g_X1t[((size_t)b * cD + d0 + dl) * cN + n] = s[nl][dl];
    }
}

// ---------------- launch 3: attn GEMM + gamma1 + residual + norm2 ----------------
__global__ void __launch_bounds__(256) k_attn(const float* __restrict__ sfs) {
    __shared__ int sx[64][52];
    __shared__ int sw[49][52];
    const float sf0 = sfs[0], sf1 = sfs[1], sf2 = sfs[2], sf3 = sfs[3], sf4 = sfs[4];
    const float r2 = __fdiv_rn(__fmul_rn(sf1, wsf_of(1)), sf2);
    const float r3 = __fdiv_rn(__fmul_rn(sf2, wsf_of(2)), sf3);
    const float rid1 = __fdiv_rn(sf0, sf3);
    const float r4 = __fdiv_rn(__fmul_rn(sf3, wsf_of(3)), sf4);

    const int b = blockIdx.z, d0 = blockIdx.y * 64, o0 = blockIdx.x * 49;
    const int* X1ti = (const int*)g_X1t;
    for (int i = threadIdx.x; i < 64 * 49; i += 256) {
        int r = i / 49, c2 = i % 49;
        sx[r][c2] = X1ti[((size_t)b * cD + d0 + r) * 49 + c2];
    }
    const int* awi = (const int*)g_aw8;
    for (int i = threadIdx.x; i < 49 * 49; i += 256) {
        int r = i / 49, c2 = i % 49;
        sw[r][c2] = awi[(o0 + r) * 49 + c2];
    }
    __syncthreads();
    for (int j = threadIdx.x; j < 49 * 64; j += 256) {
        int d = j & 63, o = j >> 6;
        int acc = g_ab32[o0 + o];
        #pragma unroll
        for (int w4 = 0; w4 < 12; w4++) {
            int4 xa = *(const int4*)&sx[d][w4 * 4];
            int4 wa = *(const int4*)&sw[o][w4 * 4];
            acc = __dp4a(xa.x, wa.x, acc);
            acc = __dp4a(xa.y, wa.y, acc);
            acc = __dp4a(xa.z, wa.z, acc);
            acc = __dp4a(xa.w, wa.w, acc);
        }
        acc = __dp4a(sx[d][48], sw[o][48], acc);
        int dg = d0 + d;
        int x2 = clamp8(rni(__fmul_rn((float)acc, r2)));
        int gg = x2 * g_g1wi[dg];
        size_t gi = (size_t)b * cN * cD + (size_t)(o0 + o) * cD + dg;
        int x0v = g_X0[gi];
        int x3 = clamp8(rni(__fmul_rn((float)gg, r3)) + rni(__fmul_rn((float)x0v, rid1)));
        g_X3[gi] = (signed char)x3;
        int z4 = x3 * g_n2wi[dg] + g_b2i[dg];
        g_X4[gi] = (signed char)clamp8(rni(__fmul_rn((float)z4, r4)));
    }
}

// ---------------- hybrid tensor(IMMA 64 cols) + dp4a (64 cols), cp.async 3-stage ----------------
__device__ __forceinline__ void imma(int& c0, int& c1, int& c2, int& c3,
                                     int a0, int a1, int a2, int a3, int b0, int b1) {
    asm volatile(
        "mma.sync.aligned.m16n8k32.row.col.s32.s8.s8.s32 "
        "{%0,%1,%2,%3}, {%4,%5,%6,%7}, {%8,%9}, {%0,%1,%2,%3};"
        : "+r"(c0), "+r"(c1), "+r"(c2), "+r"(c3)
        : "r"(a0), "r"(a1), "r"(a2), "r"(a3), "r"(b0), "r"(b1));
}
__device__ __forceinline__ void ldsm4(int& r0, int& r1, int& r2, int& r3, uint32_t a) {
    asm volatile("ldmatrix.sync.aligned.m8n8.x4.shared.b16 {%0,%1,%2,%3}, [%4];"
                 : "=r"(r0), "=r"(r1), "=r"(r2), "=r"(r3) : "r"(a));
}
__device__ __forceinline__ void ldsm2(int& r0, int& r1, uint32_t a) {
    asm volatile("ldmatrix.sync.aligned.m8n8.x2.shared.b16 {%0,%1}, [%2];"
                 : "=r"(r0), "=r"(r1) : "r"(a));
}

constexpr int TPAD = 36;
constexpr int BUFI = 128 * TPAD;       // 4608 ints
constexpr int BS_OFF = 3 * BUFI;       // 13824 ints
constexpr int FC_SMEM = 2 * 3 * BUFI * 4;  // 110592 bytes

__device__ __forceinline__ void hybrid_mainloop(
    const char* __restrict__ A, const char* __restrict__ B, int ldb /*bytes*/, int KI,
    int m0, int n0, int phase, int* sdyn, int acc[64])
{
    const int tid = threadIdx.x;
    const int lane = tid & 31, wid = tid >> 5;
    const int SEG = tid & 7, RG = tid >> 3;
    const uint32_t sbase = smem_u32(sdyn);
    const uint32_t asB = sbase, bsB = sbase + BS_OFF * 4;

    const int warp_m = (wid & 1) * 64, warp_n = (wid >> 1) * 32;
    const int arow_l = warp_m + (lane & 7) + ((lane >> 3) & 1) * 8;
    const uint32_t aAddr = asB + (uint32_t)arow_l * 144 + (lane >> 4) * 16;
    const int brow_l = warp_n + (lane & 7);
    const uint32_t bAddr = bsB + (uint32_t)brow_l * 144 + ((lane >> 3) & 1) * 16;
    const int ry = (tid & 127) >> 3, tx = tid & 7;

    #pragma unroll
    for (int i = 0; i < 64; i++) acc[i] = 0;

    const char* aSrc = A + (long long)(m0 + RG) * ldb + SEG * 16;
    const char* bSrc = B + (long long)(n0 + RG) * ldb + SEG * 16;
    const uint32_t aDst = asB + (uint32_t)RG * 144 + SEG * 16;
    const uint32_t bDst = bsB + (uint32_t)RG * 144 + SEG * 16;

    // chunk-order rotation: accumulate K in rotated order (int adds are exact, order-free)
    #define FC_ISSUE(kc) do {                                                     \
        int _c = (kc) + phase; if (_c >= KI) _c -= KI;                             \
        int _buf = (kc) % 3;                                                      \
        uint32_t _ad = aDst + _buf * (BUFI * 4);                                  \
        uint32_t _bd = bDst + _buf * (BUFI * 4);                                  \
        const char* _as = aSrc + _c * 128;                                        \
        const char* _bs = bSrc + _c * 128;                                        \
        _Pragma("unroll")                                                         \
        for (int _p = 0; _p < 4; _p++) {                                          \
            CP16(_ad + _p * (32 * 144), _as + (long long)(32 * _p) * ldb);        \
            CP16(_bd + _p * (32 * 144), _bs + (long long)(32 * _p) * ldb);        \
        }                                                                         \
        CPCOMMIT();                                                               \
    } while (0)

    FC_ISSUE(0);
    if (KI > 1) FC_ISSUE(1);

    for (int kc = 0; kc < KI; kc++) {
        if (kc + 1 < KI) { CPWAIT(1); } else { CPWAIT(0); }
        __syncthreads();
        if (kc + 2 < KI) FC_ISSUE(kc + 2);
        const int buf = kc % 3;
        if (wid < 4) {
            const uint32_t aT = aAddr + buf * (BUFI * 4);
            const uint32_t bT = bAddr + buf * (BUFI * 4);
            #pragma unroll
            for (int ks = 0; ks < 4; ks++) {
                int a[4][4], b[4][2];
                #pragma unroll
                for (int ma = 0; ma < 4; ma++)
                    ldsm4(a[ma][0], a[ma][1], a[ma][2], a[ma][3], aT + ma * (16 * 144) + ks * 32);
                #pragma unroll
                for (int na = 0; na < 4; na++)
                    ldsm2(b[na][0], b[na][1], bT + na * (8 * 144) + ks * 32);
                #pragma unroll
                for (int ma = 0; ma < 4; ma++)
                    #pragma unroll
                    for (int na = 0; na < 4; na++) {
                        int* c = &acc[ma * 16 + na * 4];
                        imma(c[0], c[1], c[2], c[3],
                             a[ma][0], a[ma][1], a[ma][2], a[ma][3], b[na][0], b[na][1]);
                    }
            }
        } else {
            const int* Abuf = sdyn + buf * BUFI;
            const int* Bbuf = sdyn + BS_OFF + buf * BUFI;
            #pragma unroll
            for (int kwg = 0; kwg < 8; kwg++) {
                int4 b4[8];
                #pragma unroll
                for (int j = 0; j < 8; j++)
                    b4[j] = *(const int4*)&Bbuf[(64 + tx + 8 * j) * TPAD + kwg * 4];
                // software-pipelined a4: prefetch next row before consuming current
                int4 a4 = *(const int4*)&Abuf[(ry) * TPAD + kwg * 4];
                #pragma unroll
                for (int i = 0; i < 8; i++) {
                    int4 a4n;
                    if (i < 7) a4n = *(const int4*)&Abuf[(ry + 16 * (i + 1)) * TPAD + kwg * 4];
                    #pragma unroll
                    for (int j = 0; j < 8; j++) {
                        int v = acc[i * 8 + j];
                        v = __dp4a(a4.x, b4[j].x, v);
                        v = __dp4a(a4.y, b4[j].y, v);
                        v = __dp4a(a4.z, b4[j].z, v);
                        v = __dp4a(a4.w, b4[j].w, v);
                        acc[i * 8 + j] = v;
                    }
                    if (i < 7) a4 = a4n;
                }
            }
        }
    }
    #undef FC_ISSUE
}

// ---------------- launch 4: fc1 -> relu+requant int8 X5 ----------------
__global__ void __launch_bounds__(256, 2) k_fc1(const float* __restrict__ sfs) {
    extern __shared__ int sdyn[];
    const int m0 = blockIdx.y * 128, h0 = blockIdx.x * 128;
    const int phase = ((blockIdx.x ^ blockIdx.y) & 1) * 3;
    int acc[64];
    hybrid_mainloop((const char*)g_X4, (const char*)g_f1w8, 768, 6, m0, h0, phase, sdyn, acc);

    const float r5 = __fdiv_rn(__fmul_rn(sfs[4], wsf_of(4)), sfs[5]);
    const int lane = threadIdx.x & 31, wid = threadIdx.x >> 5;
    if (wid < 4) {
        const int warp_m = (wid & 1) * 64, warp_n = (wid >> 1) * 32;
        #pragma unroll
        for (int ma = 0; ma < 4; ma++) {
            int row0 = m0 + warp_m + ma * 16 + (lane >> 2);
            #pragma unroll
            for (int na = 0; na < 4; na++) {
                int col0 = h0 + warp_n + na * 8 + (lane & 3) * 2;
                int bias0 = g_f1b[col0], bias1 = g_f1b[col0 + 1];
                #pragma unroll
                for (int h = 0; h < 2; h++) {
                    int row = row0 + h * 8;
                    int t0 = acc[ma * 16 + na * 4 + h * 2 + 0] + bias0; t0 = t0 > 0 ? t0 : 0;
                    int t1 = acc[ma * 16 + na * 4 + h * 2 + 1] + bias1; t1 = t1 > 0 ? t1 : 0;
                    int q0 = min(127, rni(__fmul_rn((float)t0, r5)));
                    int q1 = min(127, rni(__fmul_rn((float)t1, r5)));
                    *(short*)&g_X5[(long long)row * cH + col0] = (short)((q0 & 0xff) | (q1 << 8));
                }
            }
        }
    } else {
        const int ry = (threadIdx.x & 127) >> 3, tx = threadIdx.x & 7;
        int bias[8];
        #pragma unroll
        for (int j = 0; j < 8; j++) bias[j] = g_f1b[h0 + 64 + tx + 8 * j];
        #pragma unroll
        for (int i = 0; i < 8; i++) {
            long long rowb = (long long)(m0 + ry + 16 * i) * cH + h0 + 64 + tx;
            #pragma unroll
            for (int j = 0; j < 8; j++) {
                int t = acc[i * 8 + j] + bias[j]; t = t > 0 ? t : 0;
                g_X5[rowb + 8 * j] = (signed char)min(127, rni(__fmul_rn((float)t, r5)));
            }
        }
    }
}

// ---------------- launch 5: fc2 + gamma2 + residual + dequant -> fp32 out ----------------
__global__ void __launch_bounds__(256, 2) k_fc2(float* __restrict__ out,
                                                const float* __restrict__ sfs) {
    extern __shared__ int sdyn[];
    const int m0 = blockIdx.y * 128, h0 = blockIdx.x * 128;
    const int phase = ((blockIdx.x ^ blockIdx.y) & 1) * 12;
    int acc[64];
    hybrid_mainloop((const char*)g_X5, (const char*)g_f2w8, 3072, 24, m0, h0, phase, sdyn, acc);

    const float sf3 = sfs[3], sf5 = sfs[5], sf6 = sfs[6], sf7 = sfs[7];
    const float r6 = __fdiv_rn(__fmul_rn(sf5, wsf_of(5)), sf6);
    const float r7 = __fdiv_rn(__fmul_rn(sf6, wsf_of(6)), sf7);
    const float rid2 = __fdiv_rn(sf3, sf7);
    const int lane = threadIdx.x & 31, wid = threadIdx.x >> 5;
    if (wid < 4) {
        const int warp_m = (wid & 1) * 64, warp_n = (wid >> 1) * 32;
        #pragma unroll
        for (int ma = 0; ma < 4; ma++) {
            int row0 = m0 + warp_m + ma * 16 + (lane >> 2);
            #pragma unroll
            for (int na = 0; na < 4; na++) {
                int col0 = h0 + warp_n + na * 8 + (lane & 3) * 2;
                int bias0 = g_f2b[col0], bias1 = g_f2b[col0 + 1];
                int gw0 = g_g2wi[col0],  gw1 = g_g2wi[col0 + 1];
                #pragma unroll
                for (int h = 0; h < 2; h++) {
                    long long base = (long long)(row0 + h * 8) * cD + col0;
                    int x60 = clamp8(rni(__fmul_rn((float)(acc[ma * 16 + na * 4 + h * 2 + 0] + bias0), r6)));
                    int x61 = clamp8(rni(__fmul_rn((float)(acc[ma * 16 + na * 4 + h * 2 + 1] + bias1), r6)));
                    int x3a = g_X3[base], x3b = g_X3[base + 1];
                    int v0 = clamp8(rni(__fmul_rn((float)(x60 * gw0), r7)) + rni(__fmul_rn((float)x3a, rid2)));
                    int v1 = clamp8(rni(__fmul_rn((float)(x61 * gw1), r7)) + rni(__fmul_rn((float)x3b, rid2)));
                    float2 o;
                    o.x = __fmul_rn((float)v0, sf7);
                    o.y = __fmul_rn((float)v1, sf7);
                    *(float2*)(out + base) = o;
                }
            }
        }
    } else {
        const int ry = (threadIdx.x & 127) >> 3, tx = threadIdx.x & 7;
        int bias[8], gw[8];
        #pragma unroll
        for (int j = 0; j < 8; j++) {
            bias[j] = g_f2b[h0 + 64 + tx + 8 * j];
            gw[j]   = g_g2wi[h0 + 64 + tx + 8 * j];
        }
        #pragma unroll
        for (int i = 0; i < 8; i++) {
            long long rowb = (long long)(m0 + ry + 16 * i) * cD + h0 + 64 + tx;
            #pragma unroll
            for (int j = 0; j < 8; j++) {
                int x6 = clamp8(rni(__fmul_rn((float)(acc[i * 8 + j] + bias[j]), r6)));
                int gg = x6 * gw[j];
                int x3v = g_X3[rowb + 8 * j];
                int v = clamp8(rni(__fmul_rn((float)gg, r7)) + rni(__fmul_rn((float)x3v, rid2)));
                out[rowb + 8 * j] = __fmul_rn((float)v, sf7);
            }
        }
    }
}

__global__ void k_tail(float* out, long long start, long long total, const float* act_sfs) {
    long long i = start + (long long)blockIdx.x * 256 + threadIdx.x;
    if (i < total) out[i] = act_sfs[7];
}

extern "C" void kernel_launch(void* const* d_in, const int* in_sizes, int n_in,
                              void* d_out, int out_size) {
    const float* x   = (const float*)d_in[0];
    const float* n1w = (const float*)d_in[1];
    const float* n1b = (const float*)d_in[2];
    const float* aw  = (const float*)d_in[3];
    const float* ab  = (const float*)d_in[4];
    const float* g1  = (const float*)d_in[5];
    const float* n2w = (const float*)d_in[6];
    const float* n2b = (const float*)d_in[7];
    const float* f1w = (const float*)d_in[8];
    const float* f1b = (const float*)d_in[9];
    const float* f2w = (const float*)d_in[10];
    const float* f2b = (const float*)d_in[11];
    const float* g2  = (const float*)d_in[12];
    const float* sfs = (const float*)d_in[13];
    float* out = (float*)d_out;

    cudaFuncSetAttribute(k_fc1, cudaFuncAttributeMaxDynamicSharedMemorySize, FC_SMEM);
    cudaFuncSetAttribute(k_fc2, cudaFuncAttributeMaxDynamicSharedMemorySize, FC_SMEM);

    k_maxabs<<<585, 256>>>(n1w, aw, g1, n2w, f1w, f2w, g2);
    k_qwin<<<QW_BLOCKS + IN_BLOCKS, 256>>>(n1w, n1b, aw, ab, g1, n2w, n2b,
                                           f1w, f1b, f2w, f2b, g2, x, sfs);
    {
        dim3 g(4, cD / 64, cB);
        k_attn<<<g, 256>>>(sfs);
    }
    {
        dim3 g(cH / 128, cM / 128);
        k_fc1<<<g, 256, FC_SMEM>>>(sfs);
    }
    {
        dim3 g(cD / 128, cM / 128);
        k_fc2<<<g, 256, FC_SMEM>>>(out, sfs);
    }
    long long total = (long long)out_size;
    if (total > (long long)BNDTOT) {
        long long tail = total - BNDTOT;
        k_tail<<<(int)((tail + 255) / 256), 256>>>(out, BNDTOT, total, sfs);
    }
}

// round 15
// speedup vs baseline: 1.0510x; 1.0510x over previous
#include <cuda_runtime.h>
#include <cstdint>

constexpr int cB = 64, cN = 196, cD = 768, cH = 3072;
constexpr int cM = cB * cN;            // 12544
constexpr int BNDTOT = cB * cN * cD;   // 9633792
constexpr int HDTOT = cH * cD;         // 2359296

__device__ int g_maxbits[7];           // zero-init; atomicMax idempotent across graph replays

__device__ signed char g_X0[BNDTOT];
__device__ signed char g_X1t[BNDTOT];          // [B,D,N]
__device__ signed char g_X3[BNDTOT];
__device__ signed char g_X4[BNDTOT];
__device__ signed char g_X5[(long long)cM * cH];
__device__ signed char g_aw8[cN * cN];
__device__ int  g_ab32[cN];
__device__ signed char g_f1w8[HDTOT];
__device__ int  g_f1b[cH];
__device__ signed char g_f2w8[HDTOT];
__device__ int  g_f2b[cD];
__device__ int  g_g1wi[cD], g_n2wi[cD], g_b2i[cD], g_g2wi[cD];

__device__ __forceinline__ int clamp8(int v) { return max(-128, min(127, v)); }
__device__ __forceinline__ int rni(float f)  { return __float2int_rn(f); }
__device__ __forceinline__ float wsf_of(int slot) {
    return __fdiv_rn(__int_as_float(g_maxbits[slot]), 127.0f);
}

__device__ __forceinline__ uint32_t smem_u32(const void* p) {
    uint32_t a;
    asm("{ .reg .u64 t; cvta.to.shared.u64 t, %1; cvt.u32.u64 %0, t; }" : "=r"(a) : "l"(p));
    return a;
}

#define CP16(d, s) asm volatile("cp.async.cg.shared.global [%0], [%1], 16;" :: "r"(d), "l"(s))
#define CPCOMMIT() asm volatile("cp.async.commit_group;" ::: "memory")
#define CPWAIT(n)  asm volatile("cp.async.wait_group %0;" :: "n"(n) : "memory")

// ---------------- launch 1: maxabs reductions ----------------
__global__ void k_maxabs(const float* n1w, const float* aw, const float* g1,
                         const float* n2w, const float* f1, const float* f2, const float* g2) {
    int bid = blockIdx.x;
    const float* src; int slot, n, base;
    if (bid < 288)      { src = f1; slot = 4; n = HDTOT;   base = bid; }
    else if (bid < 576) { src = f2; slot = 5; n = HDTOT;   base = bid - 288; }
    else if (bid < 581) { src = aw; slot = 1; n = cN * cN; base = bid - 576; }
    else {
        base = 0; n = cD;
        int s = bid - 581;
        if (s == 0)      { src = n1w; slot = 0; }
        else if (s == 1) { src = g1;  slot = 2; }
        else if (s == 2) { src = n2w; slot = 3; }
        else             { src = g2;  slot = 6; }
    }
    int start = base * 8192;
    int end = min(n, start + 8192);
    float m = 0.f;
    for (int i = start + threadIdx.x; i < end; i += 256) m = fmaxf(m, fabsf(src[i]));
    #pragma unroll
    for (int o = 16; o; o >>= 1) m = fmaxf(m, __shfl_xor_sync(0xffffffffu, m, o));
    __shared__ float sm[8];
    if ((threadIdx.x & 31) == 0) sm[threadIdx.x >> 5] = m;
    __syncthreads();
    if (threadIdx.x == 0) {
        for (int i = 1; i < 8; i++) m = fmaxf(m, sm[i]);
        atomicMax(&g_maxbits[slot], __float_as_int(m));
    }
}

// ---------------- launch 2: fused quantw + input ----------------
constexpr int HD4 = HDTOT / 4;
constexpr int RESTQ = cN * cN + cN + cH + cD + 4 * cD;
constexpr int TOTQ = 2 * HD4 + RESTQ;
constexpr int QW_BLOCKS = (TOTQ + 255) / 256;
constexpr int IN_BLOCKS = 12 * 4 * cB;   // 3072

__global__ void k_qwin(const float* n1w, const float* n1b, const float* aw, const float* ab,
                       const float* g1, const float* n2w, const float* n2b,
                       const float* f1w, const float* f1b, const float* f2w, const float* f2b,
                       const float* g2, const float* __restrict__ x,
                       const float* __restrict__ sfs) {
    __shared__ signed char s[64][68];
    __shared__ int swv[64], sbv[64];
    if (blockIdx.x < QW_BLOCKS) {
        const float w1 = wsf_of(1), w2 = wsf_of(2), w3 = wsf_of(3);
        const float w4 = wsf_of(4), w5 = wsf_of(5), w6 = wsf_of(6);
        const float sf1 = sfs[1], sf3 = sfs[3], sf4 = sfs[4], sf5 = sfs[5];
        const float den_ab  = __fmul_rn(sf1, w1);
        const float den_b2  = __fmul_rn(sf3, w3);
        const float den_f1b = __fmul_rn(sf4, w4);
        const float den_f2b = __fmul_rn(sf5, w5);

        int idx = blockIdx.x * 256 + threadIdx.x;
        if (idx < HD4) {
            float4 v = reinterpret_cast<const float4*>(f1w)[idx];
            char4 o;
            o.x = (signed char)clamp8(rni(__fdiv_rn(v.x, w4)));
            o.y = (signed char)clamp8(rni(__fdiv_rn(v.y, w4)));
            o.z = (signed char)clamp8(rni(__fdiv_rn(v.z, w4)));
            o.w = (signed char)clamp8(rni(__fdiv_rn(v.w, w4)));
            reinterpret_cast<char4*>(g_f1w8)[idx] = o;
            return;
        }
        idx -= HD4;
        if (idx < HD4) {
            float4 v = reinterpret_cast<const float4*>(f2w)[idx];
            char4 o;
            o.x = (signed char)clamp8(rni(__fdiv_rn(v.x, w5)));
            o.y = (signed char)clamp8(rni(__fdiv_rn(v.y, w5)));
            o.z = (signed char)clamp8(rni(__fdiv_rn(v.z, w5)));
            o.w = (signed char)clamp8(rni(__fdiv_rn(v.w, w5)));
            reinterpret_cast<char4*>(g_f2w8)[idx] = o;
            return;
        }
        idx -= HD4;
        if (idx < cN * cN) { g_aw8[idx] = (signed char)clamp8(rni(__fdiv_rn(aw[idx], w1))); return; }
        idx -= cN * cN;
        if (idx < cN) { g_ab32[idx] = rni(__fdiv_rn(ab[idx], den_ab)); return; }
        idx -= cN;
        if (idx < cH) { g_f1b[idx] = rni(__fdiv_rn(f1b[idx], den_f1b)); return; }
        idx -= cH;
        if (idx < cD) { g_f2b[idx] = rni(__fdiv_rn(f2b[idx], den_f2b)); return; }
        idx -= cD;
        if (idx < cD) { g_g1wi[idx] = rni(__fdiv_rn(g1[idx],  w2)); return; }
        idx -= cD;
        if (idx < cD) { g_n2wi[idx] = rni(__fdiv_rn(n2w[idx], w3)); return; }
        idx -= cD;
        if (idx < cD) { g_b2i[idx]  = rni(__fdiv_rn(n2b[idx], den_b2)); return; }
        idx -= cD;
        if (idx < cD) { g_g2wi[idx] = rni(__fdiv_rn(g2[idx],  w6)); return; }
        return;
    }
    // ---- input branch ----
    const float w0 = wsf_of(0);
    const float s0 = sfs[0];
    const float den_b1 = __fmul_rn(s0, w0);
    const float r1 = __fdiv_rn(den_b1, sfs[1]);
    int v = blockIdx.x - QW_BLOCKS;
    const int dt = v % 12, nt = (v / 12) % 4, b = v / 48;
    const int n0 = nt * 64, d0 = dt * 64;
    if (threadIdx.x < 64) {
        swv[threadIdx.x] = rni(__fdiv_rn(n1w[d0 + threadIdx.x], w0));
        sbv[threadIdx.x] = rni(__fdiv_rn(n1b[d0 + threadIdx.x], den_b1));
    }
    __syncthreads();
    const float* xb = x + (size_t)b * cN * cD;
    signed char* x0b = g_X0 + (size_t)b * cN * cD;
    #pragma unroll
    for (int it = 0; it < 4; it++) {
        int e = threadIdx.x + it * 256;
        int nl = e >> 4, gl = e & 15;
        int n = n0 + nl, d = d0 + gl * 4;
        if (n < cN) {
            float4 xv = *(const float4*)&xb[n * cD + d];
            int4 wv = *(const int4*)&swv[gl * 4];
            int4 bv = *(const int4*)&sbv[gl * 4];
            int xa = rni(__fdiv_rn(xv.x, s0));
            int xbq = rni(__fdiv_rn(xv.y, s0));
            int xc = rni(__fdiv_rn(xv.z, s0));
            int xd = rni(__fdiv_rn(xv.w, s0));
            char4 c0;
            c0.x = (signed char)xa; c0.y = (signed char)xbq;
            c0.z = (signed char)xc; c0.w = (signed char)xd;
            *(char4*)&x0b[n * cD + d] = c0;
            s[nl][gl * 4 + 0] = (signed char)clamp8(rni(__fmul_rn((float)(xa  * wv.x + bv.x), r1)));
            s[nl][gl * 4 + 1] = (signed char)clamp8(rni(__fmul_rn((float)(xbq * wv.y + bv.y), r1)));
            s[nl][gl * 4 + 2] = (signed char)clamp8(rni(__fmul_rn((float)(xc  * wv.z + bv.z), r1)));
            s[nl][gl * 4 + 3] = (signed char)clamp8(rni(__fmul_rn((float)(xd  * wv.w + bv.w), r1)));
        }
    }
    __syncthreads();
    #pragma unroll
    for (int it = 0; it < 16; it++) {
        int e = threadIdx.x + it * 256;
        int dl = e >> 6, nl = e & 63;
        int n = n0 + nl;
        if (n < cN) g_X1t[((size_t)b * cD + d0 + dl) * cN + n] = s[nl][dl];
    }
}

// ---------------- launch 3: attn GEMM + gamma1 + residual + norm2 ----------------
__global__ void __launch_bounds__(256) k_attn(const float* __restrict__ sfs) {
    __shared__ int sx[64][52];
    __shared__ int sw[49][52];
    const float sf0 = sfs[0], sf1 = sfs[1], sf2 = sfs[2], sf3 = sfs[3], sf4 = sfs[4];
    const float r2 = __fdiv_rn(__fmul_rn(sf1, wsf_of(1)), sf2);
    const float r3 = __fdiv_rn(__fmul_rn(sf2, wsf_of(2)), sf3);
    const float rid1 = __fdiv_rn(sf0, sf3);
    const float r4 = __fdiv_rn(__fmul_rn(sf3, wsf_of(3)), sf4);

    const int b = blockIdx.z, d0 = blockIdx.y * 64, o0 = blockIdx.x * 49;
    const int* X1ti = (const int*)g_X1t;
    for (int i = threadIdx.x; i < 64 * 49; i += 256) {
        int r = i / 49, c2 = i % 49;
        sx[r][c2] = X1ti[((size_t)b * cD + d0 + r) * 49 + c2];
    }
    const int* awi = (const int*)g_aw8;
    for (int i = threadIdx.x; i < 49 * 49; i += 256) {
        int r = i / 49, c2 = i % 49;
        sw[r][c2] = awi[(o0 + r) * 49 + c2];
    }
    __syncthreads();
    for (int j = threadIdx.x; j < 49 * 64; j += 256) {
        int d = j & 63, o = j >> 6;
        int acc = g_ab32[o0 + o];
        #pragma unroll
        for (int w4 = 0; w4 < 12; w4++) {
            int4 xa = *(const int4*)&sx[d][w4 * 4];
            int4 wa = *(const int4*)&sw[o][w4 * 4];
            acc = __dp4a(xa.x, wa.x, acc);
            acc = __dp4a(xa.y, wa.y, acc);
            acc = __dp4a(xa.z, wa.z, acc);
            acc = __dp4a(xa.w, wa.w, acc);
        }
        acc = __dp4a(sx[d][48], sw[o][48], acc);
        int dg = d0 + d;
        int x2 = clamp8(rni(__fmul_rn((float)acc, r2)));
        int gg = x2 * g_g1wi[dg];
        size_t gi = (size_t)b * cN * cD + (size_t)(o0 + o) * cD + dg;
        int x0v = g_X0[gi];
        int x3 = clamp8(rni(__fmul_rn((float)gg, r3)) + rni(__fmul_rn((float)x0v, rid1)));
        g_X3[gi] = (signed char)x3;
        int z4 = x3 * g_n2wi[dg] + g_b2i[dg];
        g_X4[gi] = (signed char)clamp8(rni(__fmul_rn((float)z4, r4)));
    }
}

// ---------------- hybrid tensor(IMMA 64 cols) + dp4a (64 cols), cp.async 3-stage ----------------
__device__ __forceinline__ void imma(int& c0, int& c1, int& c2, int& c3,
                                     int a0, int a1, int a2, int a3, int b0, int b1) {
    asm volatile(
        "mma.sync.aligned.m16n8k32.row.col.s32.s8.s8.s32 "
        "{%0,%1,%2,%3}, {%4,%5,%6,%7}, {%8,%9}, {%0,%1,%2,%3};"
        : "+r"(c0), "+r"(c1), "+r"(c2), "+r"(c3)
        : "r"(a0), "r"(a1), "r"(a2), "r"(a3), "r"(b0), "r"(b1));
}
__device__ __forceinline__ void ldsm4(int& r0, int& r1, int& r2, int& r3, uint32_t a) {
    asm volatile("ldmatrix.sync.aligned.m8n8.x4.shared.b16 {%0,%1,%2,%3}, [%4];"
                 : "=r"(r0), "=r"(r1), "=r"(r2), "=r"(r3) : "r"(a));
}
__device__ __forceinline__ void ldsm2(int& r0, int& r1, uint32_t a) {
    asm volatile("ldmatrix.sync.aligned.m8n8.x2.shared.b16 {%0,%1}, [%2];"
                 : "=r"(r0), "=r"(r1) : "r"(a));
}

constexpr int TPAD = 36;
constexpr int BUFI = 128 * TPAD;       // 4608 ints
constexpr int BS_OFF = 3 * BUFI;       // 13824 ints
constexpr int FC_SMEM = 2 * 3 * BUFI * 4;  // 110592 bytes

__device__ __forceinline__ void hybrid_mainloop(
    const char* __restrict__ A, const char* __restrict__ B, int ldb /*bytes*/, int KI,
    int m0, int n0, int* sdyn, int acc[64])
{
    const int tid = threadIdx.x;
    const int lane = tid & 31, wid = tid >> 5;
    const int SEG = tid & 7, RG = tid >> 3;
    const uint32_t sbase = smem_u32(sdyn);
    const uint32_t asB = sbase, bsB = sbase + BS_OFF * 4;

    const int warp_m = (wid & 1) * 64, warp_n = (wid >> 1) * 32;
    const int arow_l = warp_m + (lane & 7) + ((lane >> 3) & 1) * 8;
    const uint32_t aAddr = asB + (uint32_t)arow_l * 144 + (lane >> 4) * 16;
    const int brow_l = warp_n + (lane & 7);
    const uint32_t bAddr = bsB + (uint32_t)brow_l * 144 + ((lane >> 3) & 1) * 16;
    const int ry = (tid & 127) >> 3, tx = tid & 7;

    #pragma unroll
    for (int i = 0; i < 64; i++) acc[i] = 0;

    const char* aSrc = A + (long long)(m0 + RG) * ldb + SEG * 16;
    const char* bSrc = B + (long long)(n0 + RG) * ldb + SEG * 16;
    const uint32_t aDst = asB + (uint32_t)RG * 144 + SEG * 16;
    const uint32_t bDst = bsB + (uint32_t)RG * 144 + SEG * 16;

    #define FC_ISSUE(kc) do {                                                     \
        int _buf = (kc) % 3;                                                      \
        uint32_t _ad = aDst + _buf * (BUFI * 4);                                  \
        uint32_t _bd = bDst + _buf * (BUFI * 4);                                  \
        const char* _as = aSrc + (kc) * 128;                                      \
        const char* _bs = bSrc + (kc) * 128;                                      \
        _Pragma("unroll")                                                         \
        for (int _p = 0; _p < 4; _p++) {                                          \
            CP16(_ad + _p * (32 * 144), _as + (long long)(32 * _p) * ldb);        \
            CP16(_bd + _p * (32 * 144), _bs + (long long)(32 * _p) * ldb);        \
        }                                                                         \
        CPCOMMIT();                                                               \
    } while (0)

    FC_ISSUE(0);
    if (KI > 1) FC_ISSUE(1);

    for (int kc = 0; kc < KI; kc++) {
        if (kc + 1 < KI) { CPWAIT(1); } else { CPWAIT(0); }
        __syncthreads();
        if (kc + 2 < KI) FC_ISSUE(kc + 2);
        const int buf = kc % 3;
        if (wid < 4) {
            const uint32_t aT = aAddr + buf * (BUFI * 4);
            const uint32_t bT = bAddr + buf * (BUFI * 4);
            #pragma unroll
            for (int ks = 0; ks < 4; ks++) {
                int a[4][4], b[4][2];
                #pragma unroll
                for (int ma = 0; ma < 4; ma++)
                    ldsm4(a[ma][0], a[ma][1], a[ma][2], a[ma][3], aT + ma * (16 * 144) + ks * 32);
                #pragma unroll
                for (int na = 0; na < 4; na++)
                    ldsm2(b[na][0], b[na][1], bT + na * (8 * 144) + ks * 32);
                #pragma unroll
                for (int ma = 0; ma < 4; ma++)
                    #pragma unroll
                    for (int na = 0; na < 4; na++) {
                        int* c = &acc[ma * 16 + na * 4];
                        imma(c[0], c[1], c[2], c[3],
                             a[ma][0], a[ma][1], a[ma][2], a[ma][3], b[na][0], b[na][1]);
                    }
            }
        } else {
            const int* Abuf = sdyn + buf * BUFI;
            const int* Bbuf = sdyn + BS_OFF + buf * BUFI;
            #pragma unroll
            for (int kwg = 0; kwg < 8; kwg++) {
                int4 b4[8];
                #pragma unroll
                for (int j = 0; j < 8; j++)
                    b4[j] = *(const int4*)&Bbuf[(64 + tx + 8 * j) * TPAD + kwg * 4];
                #pragma unroll
                for (int i = 0; i < 8; i++) {
                    int4 a4 = *(const int4*)&Abuf[(ry + 16 * i) * TPAD + kwg * 4];
                    #pragma unroll
                    for (int j = 0; j < 8; j++) {
                        int v = acc[i * 8 + j];
                        v = __dp4a(a4.x, b4[j].x, v);
                        v = __dp4a(a4.y, b4[j].y, v);
                        v = __dp4a(a4.z, b4[j].z, v);
                        v = __dp4a(a4.w, b4[j].w, v);
                        acc[i * 8 + j] = v;
                    }
                }
            }
        }
    }
    #undef FC_ISSUE
}

// ---------------- launch 4: fc1 -> relu+requant int8 X5 ----------------
__global__ void __launch_bounds__(256, 2) k_fc1(const float* __restrict__ sfs) {
    extern __shared__ int sdyn[];
    const int m0 = blockIdx.y * 128, h0 = blockIdx.x * 128;
    int acc[64];
    hybrid_mainloop((const char*)g_X4, (const char*)g_f1w8, 768, 6, m0, h0, sdyn, acc);

    const float r5 = __fdiv_rn(__fmul_rn(sfs[4], wsf_of(4)), sfs[5]);
    const int lane = threadIdx.x & 31, wid = threadIdx.x >> 5;
    if (wid < 4) {
        const int warp_m = (wid & 1) * 64, warp_n = (wid >> 1) * 32;
        #pragma unroll
        for (int ma = 0; ma < 4; ma++) {
            int row0 = m0 + warp_m + ma * 16 + (lane >> 2);
            #pragma unroll
            for (int na = 0; na < 4; na++) {
                int col0 = h0 + warp_n + na * 8 + (lane & 3) * 2;
                int bias0 = g_f1b[col0], bias1 = g_f1b[col0 + 1];
                #pragma unroll
                for (int h = 0; h < 2; h++) {
                    int row = row0 + h * 8;
                    int t0 = acc[ma * 16 + na * 4 + h * 2 + 0] + bias0; t0 = t0 > 0 ? t0 : 0;
                    int t1 = acc[ma * 16 + na * 4 + h * 2 + 1] + bias1; t1 = t1 > 0 ? t1 : 0;
                    int q0 = min(127, rni(__fmul_rn((float)t0, r5)));
                    int q1 = min(127, rni(__fmul_rn((float)t1, r5)));
                    *(short*)&g_X5[(long long)row * cH + col0] = (short)((q0 & 0xff) | (q1 << 8));
                }
            }
        }
    } else {
        const int ry = (threadIdx.x & 127) >> 3, tx = threadIdx.x & 7;
        int bias[8];
        #pragma unroll
        for (int j = 0; j < 8; j++) bias[j] = g_f1b[h0 + 64 + tx + 8 * j];
        #pragma unroll
        for (int i = 0; i < 8; i++) {
            long long rowb = (long long)(m0 + ry + 16 * i) * cH + h0 + 64 + tx;
            #pragma unroll
            for (int j = 0; j < 8; j++) {
                int t = acc[i * 8 + j] + bias[j]; t = t > 0 ? t : 0;
                g_X5[rowb + 8 * j] = (signed char)min(127, rni(__fmul_rn((float)t, r5)));
            }
        }
    }
}

// ---------------- launch 5: fc2 + gamma2 + residual + dequant -> fp32 out ----------------
__global__ void __launch_bounds__(256, 2) k_fc2(float* __restrict__ out,
                                                const float* __restrict__ sfs) {
    extern __shared__ int sdyn[];
    const int m0 = blockIdx.y * 128, h0 = blockIdx.x * 128;
    int acc[64];
    hybrid_mainloop((const char*)g_X5, (const char*)g_f2w8, 3072, 24, m0, h0, sdyn, acc);

    const float sf3 = sfs[3], sf5 = sfs[5], sf6 = sfs[6], sf7 = sfs[7];
    const float r6 = __fdiv_rn(__fmul_rn(sf5, wsf_of(5)), sf6);
    const float r7 = __fdiv_rn(__fmul_rn(sf6, wsf_of(6)), sf7);
    const float rid2 = __fdiv_rn(sf3, sf7);
    const int lane = threadIdx.x & 31, wid = threadIdx.x >> 5;
    if (wid < 4) {
        const int warp_m = (wid & 1) * 64, warp_n = (wid >> 1) * 32;
        #pragma unroll
        for (int ma = 0; ma < 4; ma++) {
            int row0 = m0 + warp_m + ma * 16 + (lane >> 2);
            #pragma unroll
            for (int na = 0; na < 4; na++) {
                int col0 = h0 + warp_n + na * 8 + (lane & 3) * 2;
                int bias0 = g_f2b[col0], bias1 = g_f2b[col0 + 1];
                int gw0 = g_g2wi[col0],  gw1 = g_g2wi[col0 + 1];
                #pragma unroll
                for (int h = 0; h < 2; h++) {
                    long long base = (long long)(row0 + h * 8) * cD + col0;
                    int x60 = clamp8(rni(__fmul_rn((float)(acc[ma * 16 + na * 4 + h * 2 + 0] + bias0), r6)));
                    int x61 = clamp8(rni(__fmul_rn((float)(acc[ma * 16 + na * 4 + h * 2 + 1] + bias1), r6)));
                    short xs = *(const short*)&g_X3[base];
                    int x3a = (signed char)(xs & 0xff);
                    int x3b = (int)(xs >> 8);
                    int v0 = clamp8(rni(__fmul_rn((float)(x60 * gw0), r7)) + rni(__fmul_rn((float)x3a, rid2)));
                    int v1 = clamp8(rni(__fmul_rn((float)(x61 * gw1), r7)) + rni(__fmul_rn((float)x3b, rid2)));
                    float2 o;
                    o.x = __fmul_rn((float)v0, sf7);
                    o.y = __fmul_rn((float)v1, sf7);
                    *(float2*)(out + base) = o;
                }
            }
        }
    } else {
        const int ry = (threadIdx.x & 127) >> 3, tx = threadIdx.x & 7;
        int bias[8], gw[8];
        #pragma unroll
        for (int j = 0; j < 8; j++) {
            bias[j] = g_f2b[h0 + 64 + tx + 8 * j];
            gw[j]   = g_g2wi[h0 + 64 + tx + 8 * j];
        }
        #pragma unroll
        for (int i = 0; i < 8; i++) {
            long long rowb = (long long)(m0 + ry + 16 * i) * cD + h0 + 64 + tx;
            #pragma unroll
            for (int j = 0; j < 8; j++) {
                int x6 = clamp8(rni(__fmul_rn((float)(acc[i * 8 + j] + bias[j]), r6)));
                int gg = x6 * gw[j];
                int x3v = g_X3[rowb + 8 * j];
                int v = clamp8(rni(__fmul_rn((float)gg, r7)) + rni(__fmul_rn((float)x3v, rid2)));
                out[rowb + 8 * j] = __fmul_rn((float)v, sf7);
            }
        }
    }
}

__global__ void k_tail(float* out, long long start, long long total, const float* act_sfs) {
    long long i = start + (long long)blockIdx.x * 256 + threadIdx.x;
    if (i < total) out[i] = act_sfs[7];
}

extern "C" void kernel_launch(void* const* d_in, const int* in_sizes, int n_in,
                              void* d_out, int out_size) {
    const float* x   = (const float*)d_in[0];
    const float* n1w = (const float*)d_in[1];
    const float* n1b = (const float*)d_in[2];
    const float* aw  = (const float*)d_in[3];
    const float* ab  = (const float*)d_in[4];
    const float* g1  = (const float*)d_in[5];
    const float* n2w = (const float*)d_in[6];
    const float* n2b = (const float*)d_in[7];
    const float* f1w = (const float*)d_in[8];
    const float* f1b = (const float*)d_in[9];
    const float* f2w = (const float*)d_in[10];
    const float* f2b = (const float*)d_in[11];
    const float* g2  = (const float*)d_in[12];
    const float* sfs = (const float*)d_in[13];
    float* out = (float*)d_out;

    cudaFuncSetAttribute(k_fc1, cudaFuncAttributeMaxDynamicSharedMemorySize, FC_SMEM);
    cudaFuncSetAttribute(k_fc2, cudaFuncAttributeMaxDynamicSharedMemorySize, FC_SMEM);

    k_maxabs<<<585, 256>>>(n1w, aw, g1, n2w, f1w, f2w, g2);
    k_qwin<<<QW_BLOCKS + IN_BLOCKS, 256>>>(n1w, n1b, aw, ab, g1, n2w, n2b,
                                           f1w, f1b, f2w, f2b, g2, x, sfs);
    {
        dim3 g(4, cD / 64, cB);
        k_attn<<<g, 256>>>(sfs);
    }
    {
        dim3 g(cH / 128, cM / 128);
        k_fc1<<<g, 256, FC_SMEM>>>(sfs);
    }
    {
        dim3 g(cD / 128, cM / 128);
        k_fc2<<<g, 256, FC_SMEM>>>(out, sfs);
    }
    long long total = (long long)out_size;
    if (total > (long long)BNDTOT) {
        long long tail = total - BNDTOT;
        k_tail<<<(int)((tail + 255) / 256), 256>>>(out, BNDTOT, total, sfs);
    }
}

// round 16
// speedup vs baseline: 1.0526x; 1.0015x over previous
#include <cuda_runtime.h>
#include <cstdint>

constexpr int cB = 64, cN = 196, cD = 768, cH = 3072;
constexpr int cM = cB * cN;            // 12544
constexpr int BNDTOT = cB * cN * cD;   // 9633792
constexpr int HDTOT = cH * cD;         // 2359296

__device__ int g_maxbits[7];           // zero-init; atomicMax idempotent across graph replays

__device__ signed char g_X0[BNDTOT];
__device__ signed char g_X1t[BNDTOT];          // [B,D,N]
__device__ signed char g_X3[BNDTOT];
__device__ signed char g_X4[BNDTOT];
__device__ signed char g_X5[(long long)cM * cH];
__device__ signed char g_aw8[cN * cN];
__device__ int  g_ab32[cN];
__device__ signed char g_f1w8[HDTOT];
__device__ int  g_f1b[cH];
__device__ signed char g_f2w8[HDTOT];
__device__ int  g_f2b[cD];
__device__ int  g_g1wi[cD], g_n2wi[cD], g_b2i[cD], g_g2wi[cD];

__device__ __forceinline__ int clamp8(int v) { return max(-128, min(127, v)); }
__device__ __forceinline__ int rni(float f)  { return __float2int_rn(f); }
__device__ __forceinline__ float wsf_of(int slot) {
    return __fdiv_rn(__int_as_float(g_maxbits[slot]), 127.0f);
}

__device__ __forceinline__ uint32_t smem_u32(const void* p) {
    uint32_t a;
    asm("{ .reg .u64 t; cvta.to.shared.u64 t, %1; cvt.u32.u64 %0, t; }" : "=r"(a) : "l"(p));
    return a;
}

#define CP16(d, s) asm volatile("cp.async.cg.shared.global [%0], [%1], 16;" :: "r"(d), "l"(s))
#define CPCOMMIT() asm volatile("cp.async.commit_group;" ::: "memory")
#define CPWAIT(n)  asm volatile("cp.async.wait_group %0;" :: "n"(n) : "memory")

// ---------------- launch 1: maxabs reductions ----------------
__global__ void k_maxabs(const float* n1w, const float* aw, const float* g1,
                         const float* n2w, const float* f1, const float* f2, const float* g2) {
    int bid = blockIdx.x;
    const float* src; int slot, n, base;
    if (bid < 288)      { src = f1; slot = 4; n = HDTOT;   base = bid; }
    else if (bid < 576) { src = f2; slot = 5; n = HDTOT;   base = bid - 288; }
    else if (bid < 581) { src = aw; slot = 1; n = cN * cN; base = bid - 576; }
    else {
        base = 0; n = cD;
        int s = bid - 581;
        if (s == 0)      { src = n1w; slot = 0; }
        else if (s == 1) { src = g1;  slot = 2; }
        else if (s == 2) { src = n2w; slot = 3; }
        else             { src = g2;  slot = 6; }
    }
    int start = base * 8192;
    int end = min(n, start + 8192);
    float m = 0.f;
    for (int i = start + threadIdx.x; i < end; i += 256) m = fmaxf(m, fabsf(src[i]));
    #pragma unroll
    for (int o = 16; o; o >>= 1) m = fmaxf(m, __shfl_xor_sync(0xffffffffu, m, o));
    __shared__ float sm[8];
    if ((threadIdx.x & 31) == 0) sm[threadIdx.x >> 5] = m;
    __syncthreads();
    if (threadIdx.x == 0) {
        for (int i = 1; i < 8; i++) m = fmaxf(m, sm[i]);
        atomicMax(&g_maxbits[slot], __float_as_int(m));
    }
}

// ---------------- launch 2: fused quantw + input ----------------
constexpr int HD4 = HDTOT / 4;
constexpr int RESTQ = cN * cN + cN + cH + cD + 4 * cD;
constexpr int TOTQ = 2 * HD4 + RESTQ;
constexpr int QW_BLOCKS = (TOTQ + 255) / 256;
constexpr int IN_BLOCKS = 12 * 4 * cB;   // 3072

__global__ void k_qwin(const float* n1w, const float* n1b, const float* aw, const float* ab,
                       const float* g1, const float* n2w, const float* n2b,
                       const float* f1w, const float* f1b, const float* f2w, const float* f2b,
                       const float* g2, const float* __restrict__ x,
                       const float* __restrict__ sfs) {
    __shared__ signed char s[64][68];
    __shared__ int swv[64], sbv[64];
    if (blockIdx.x < QW_BLOCKS) {
        const float w1 = wsf_of(1), w2 = wsf_of(2), w3 = wsf_of(3);
        const float w4 = wsf_of(4), w5 = wsf_of(5), w6 = wsf_of(6);
        const float sf1 = sfs[1], sf3 = sfs[3], sf4 = sfs[4], sf5 = sfs[5];
        const float den_ab  = __fmul_rn(sf1, w1);
        const float den_b2  = __fmul_rn(sf3, w3);
        const float den_f1b = __fmul_rn(sf4, w4);
        const float den_f2b = __fmul_rn(sf5, w5);

        int idx = blockIdx.x * 256 + threadIdx.x;
        if (idx < HD4) {
            float4 v = reinterpret_cast<const float4*>(f1w)[idx];
            char4 o;
            o.x = (signed char)clamp8(rni(__fdiv_rn(v.x, w4)));
            o.y = (signed char)clamp8(rni(__fdiv_rn(v.y, w4)));
            o.z = (signed char)clamp8(rni(__fdiv_rn(v.z, w4)));
            o.w = (signed char)clamp8(rni(__fdiv_rn(v.w, w4)));
            reinterpret_cast<char4*>(g_f1w8)[idx] = o;
            return;
        }
        idx -= HD4;
        if (idx < HD4) {
            float4 v = reinterpret_cast<const float4*>(f2w)[idx];
            char4 o;
            o.x = (signed char)clamp8(rni(__fdiv_rn(v.x, w5)));
            o.y = (signed char)clamp8(rni(__fdiv_rn(v.y, w5)));
            o.z = (signed char)clamp8(rni(__fdiv_rn(v.z, w5)));
            o.w = (signed char)clamp8(rni(__fdiv_rn(v.w, w5)));
            reinterpret_cast<char4*>(g_f2w8)[idx] = o;
            return;
        }
        idx -= HD4;
        if (idx < cN * cN) { g_aw8[idx] = (signed char)clamp8(rni(__fdiv_rn(aw[idx], w1))); return; }
        idx -= cN * cN;
        if (idx < cN) { g_ab32[idx] = rni(__fdiv_rn(ab[idx], den_ab)); return; }
        idx -= cN;
        if (idx < cH) { g_f1b[idx] = rni(__fdiv_rn(f1b[idx], den_f1b)); return; }
        idx -= cH;
        if (idx < cD) { g_f2b[idx] = rni(__fdiv_rn(f2b[idx], den_f2b)); return; }
        idx -= cD;
        if (idx < cD) { g_g1wi[idx] = rni(__fdiv_rn(g1[idx],  w2)); return; }
        idx -= cD;
        if (idx < cD) { g_n2wi[idx] = rni(__fdiv_rn(n2w[idx], w3)); return; }
        idx -= cD;
        if (idx < cD) { g_b2i[idx]  = rni(__fdiv_rn(n2b[idx], den_b2)); return; }
        idx -= cD;
        if (idx < cD) { g_g2wi[idx] = rni(__fdiv_rn(g2[idx],  w6)); return; }
        return;
    }
    // ---- input branch ----
    const float w0 = wsf_of(0);
    const float s0 = sfs[0];
    const float den_b1 = __fmul_rn(s0, w0);
    const float r1 = __fdiv_rn(den_b1, sfs[1]);
    int v = blockIdx.x - QW_BLOCKS;
    const int dt = v % 12, nt = (v / 12) % 4, b = v / 48;
    const int n0 = nt * 64, d0 = dt * 64;
    if (threadIdx.x < 64) {
        swv[threadIdx.x] = rni(__fdiv_rn(n1w[d0 + threadIdx.x], w0));
        sbv[threadIdx.x] = rni(__fdiv_rn(n1b[d0 + threadIdx.x], den_b1));
    }
    __syncthreads();
    const float* xb = x + (size_t)b * cN * cD;
    signed char* x0b = g_X0 + (size_t)b * cN * cD;
    #pragma unroll
    for (int it = 0; it < 4; it++) {
        int e = threadIdx.x + it * 256;
        int nl = e >> 4, gl = e & 15;
        int n = n0 + nl, d = d0 + gl * 4;
        if (n < cN) {
            float4 xv = *(const float4*)&xb[n * cD + d];
            int4 wv = *(const int4*)&swv[gl * 4];
            int4 bv = *(const int4*)&sbv[gl * 4];
            int xa = rni(__fdiv_rn(xv.x, s0));
            int xbq = rni(__fdiv_rn(xv.y, s0));
            int xc = rni(__fdiv_rn(xv.z, s0));
            int xd = rni(__fdiv_rn(xv.w, s0));
            char4 c0;
            c0.x = (signed char)xa; c0.y = (signed char)xbq;
            c0.z = (signed char)xc; c0.w = (signed char)xd;
            *(char4*)&x0b[n * cD + d] = c0;
            s[nl][gl * 4 + 0] = (signed char)clamp8(rni(__fmul_rn((float)(xa  * wv.x + bv.x), r1)));
            s[nl][gl * 4 + 1] = (signed char)clamp8(rni(__fmul_rn((float)(xbq * wv.y + bv.y), r1)));
            s[nl][gl * 4 + 2] = (signed char)clamp8(rni(__fmul_rn((float)(xc  * wv.z + bv.z), r1)));
            s[nl][gl * 4 + 3] = (signed char)clamp8(rni(__fmul_rn((float)(xd  * wv.w + bv.w), r1)));
        }
    }
    __syncthreads();
    // vectorized transpose store: char4 along n (196 % 4 == 0, n-tiles 4-aligned)
    const int nvalid = min(64, cN - n0);            // 64 or 4 (nt==3)
    const int q4 = nvalid >> 2;                     // ints per row: 16 or 1
    for (int e = threadIdx.x; e < 64 * q4; e += 256) {
        int dl = e / q4, q = e - dl * q4;
        int nq = q * 4;
        char4 c;
        c.x = s[nq + 0][dl];
        c.y = s[nq + 1][dl];
        c.z = s[nq + 2][dl];
        c.w = s[nq + 3][dl];
        *(char4*)&g_X1t[((size_t)b * cD + d0 + dl) * cN + n0 + nq] = c;
    }
}

// ---------------- launch 3: attn GEMM + gamma1 + residual + norm2 (1x2 d-tiling) ----------------
__global__ void __launch_bounds__(256) k_attn(const float* __restrict__ sfs) {
    __shared__ int sx[64][52];
    __shared__ int sw[49][52];
    const float sf0 = sfs[0], sf1 = sfs[1], sf2 = sfs[2], sf3 = sfs[3], sf4 = sfs[4];
    const float r2 = __fdiv_rn(__fmul_rn(sf1, wsf_of(1)), sf2);
    const float r3 = __fdiv_rn(__fmul_rn(sf2, wsf_of(2)), sf3);
    const float rid1 = __fdiv_rn(sf0, sf3);
    const float r4 = __fdiv_rn(__fmul_rn(sf3, wsf_of(3)), sf4);

    const int b = blockIdx.z, d0 = blockIdx.y * 64, o0 = blockIdx.x * 49;
    const int* X1ti = (const int*)g_X1t;
    for (int i = threadIdx.x; i < 64 * 49; i += 256) {
        int r = i / 49, c2 = i % 49;
        sx[r][c2] = X1ti[((size_t)b * cD + d0 + r) * 49 + c2];
    }
    const int* awi = (const int*)g_aw8;
    for (int i = threadIdx.x; i < 49 * 49; i += 256) {
        int r = i / 49, c2 = i % 49;
        sw[r][c2] = awi[(o0 + r) * 49 + c2];
    }
    __syncthreads();
    for (int j = threadIdx.x; j < 49 * 32; j += 256) {
        int dl = j & 31, o = j >> 5;
        int ab0 = g_ab32[o0 + o];
        int acc0 = ab0, acc1 = ab0;
        #pragma unroll
        for (int w4 = 0; w4 < 12; w4++) {
            int4 wa  = *(const int4*)&sw[o][w4 * 4];
            int4 xa0 = *(const int4*)&sx[dl][w4 * 4];
            int4 xa1 = *(const int4*)&sx[dl + 32][w4 * 4];
            acc0 = __dp4a(xa0.x, wa.x, acc0);
            acc0 = __dp4a(xa0.y, wa.y, acc0);
            acc0 = __dp4a(xa0.z, wa.z, acc0);
            acc0 = __dp4a(xa0.w, wa.w, acc0);
            acc1 = __dp4a(xa1.x, wa.x, acc1);
            acc1 = __dp4a(xa1.y, wa.y, acc1);
            acc1 = __dp4a(xa1.z, wa.z, acc1);
            acc1 = __dp4a(xa1.w, wa.w, acc1);
        }
        {
            int wlast = sw[o][48];
            acc0 = __dp4a(sx[dl][48], wlast, acc0);
            acc1 = __dp4a(sx[dl + 32][48], wlast, acc1);
        }
        const size_t gibase = (size_t)b * cN * cD + (size_t)(o0 + o) * cD;
        #pragma unroll
        for (int h = 0; h < 2; h++) {
            int acc = h ? acc1 : acc0;
            int dg = d0 + dl + h * 32;
            int x2 = clamp8(rni(__fmul_rn((float)acc, r2)));
            int gg = x2 * g_g1wi[dg];
            size_t gi = gibase + dg;
            int x0v = g_X0[gi];
            int x3 = clamp8(rni(__fmul_rn((float)gg, r3)) + rni(__fmul_rn((float)x0v, rid1)));
            g_X3[gi] = (signed char)x3;
            int z4 = x3 * g_n2wi[dg] + g_b2i[dg];
            g_X4[gi] = (signed char)clamp8(rni(__fmul_rn((float)z4, r4)));
        }
    }
}

// ---------------- hybrid tensor(IMMA 64 cols) + dp4a (64 cols), cp.async 3-stage ----------------
__device__ __forceinline__ void imma(int& c0, int& c1, int& c2, int& c3,
                                     int a0, int a1, int a2, int a3, int b0, int b1) {
    asm volatile(
        "mma.sync.aligned.m16n8k32.row.col.s32.s8.s8.s32 "
        "{%0,%1,%2,%3}, {%4,%5,%6,%7}, {%8,%9}, {%0,%1,%2,%3};"
        : "+r"(c0), "+r"(c1), "+r"(c2), "+r"(c3)
        : "r"(a0), "r"(a1), "r"(a2), "r"(a3), "r"(b0), "r"(b1));
}
__device__ __forceinline__ void ldsm4(int& r0, int& r1, int& r2, int& r3, uint32_t a) {
    asm volatile("ldmatrix.sync.aligned.m8n8.x4.shared.b16 {%0,%1,%2,%3}, [%4];"
                 : "=r"(r0), "=r"(r1), "=r"(r2), "=r"(r3) : "r"(a));
}
__device__ __forceinline__ void ldsm2(int& r0, int& r1, uint32_t a) {
    asm volatile("ldmatrix.sync.aligned.m8n8.x2.shared.b16 {%0,%1}, [%2];"
                 : "=r"(r0), "=r"(r1) : "r"(a));
}

constexpr int TPAD = 36;
constexpr int BUFI = 128 * TPAD;       // 4608 ints
constexpr int BS_OFF = 3 * BUFI;       // 13824 ints
constexpr int FC_SMEM = 2 * 3 * BUFI * 4;  // 110592 bytes

__device__ __forceinline__ void hybrid_mainloop(
    const char* __restrict__ A, const char* __restrict__ B, int ldb /*bytes*/, int KI,
    int m0, int n0, int* sdyn, int acc[64])
{
    const int tid = threadIdx.x;
    const int lane = tid & 31, wid = tid >> 5;
    const int SEG = tid & 7, RG = tid >> 3;
    const uint32_t sbase = smem_u32(sdyn);
    const uint32_t asB = sbase, bsB = sbase + BS_OFF * 4;

    const int warp_m = (wid & 1) * 64, warp_n = (wid >> 1) * 32;
    const int arow_l = warp_m + (lane & 7) + ((lane >> 3) & 1) * 8;
    const uint32_t aAddr = asB + (uint32_t)arow_l * 144 + (lane >> 4) * 16;
    const int brow_l = warp_n + (lane & 7);
    const uint32_t bAddr = bsB + (uint32_t)brow_l * 144 + ((lane >> 3) & 1) * 16;
    const int ry = (tid & 127) >> 3, tx = tid & 7;

    #pragma unroll
    for (int i = 0; i < 64; i++) acc[i] = 0;

    const char* aSrc = A + (long long)(m0 + RG) * ldb + SEG * 16;
    const char* bSrc = B + (long long)(n0 + RG) * ldb + SEG * 16;
    const uint32_t aDst = asB + (uint32_t)RG * 144 + SEG * 16;
    const uint32_t bDst = bsB + (uint32_t)RG * 144 + SEG * 16;

    #define FC_ISSUE(kc) do {                                                     \
        int _buf = (kc) % 3;                                                      \
        uint32_t _ad = aDst + _buf * (BUFI * 4);                                  \
        uint32_t _bd = bDst + _buf * (BUFI * 4);                                  \
        const char* _as = aSrc + (kc) * 128;                                      \
        const char* _bs = bSrc + (kc) * 128;                                      \
        _Pragma("unroll")                                                         \
        for (int _p = 0; _p < 4; _p++) {                                          \
            CP16(_ad + _p * (32 * 144), _as + (long long)(32 * _p) * ldb);        \
            CP16(_bd + _p * (32 * 144), _bs + (long long)(32 * _p) * ldb);        \
        }                                                                         \
        CPCOMMIT();                                                               \
    } while (0)

    FC_ISSUE(0);
    if (KI > 1) FC_ISSUE(1);

    for (int kc = 0; kc < KI; kc++) {
        if (kc + 1 < KI) { CPWAIT(1); } else { CPWAIT(0); }
        __syncthreads();
        if (kc + 2 < KI) FC_ISSUE(kc + 2);
        const int buf = kc % 3;
        if (wid < 4) {
            const uint32_t aT = aAddr + buf * (BUFI * 4);
            const uint32_t bT = bAddr + buf * (BUFI * 4);
            #pragma unroll
            for (int ks = 0; ks < 4; ks++) {
                int a[4][4], b[4][2];
                #pragma unroll
                for (int ma = 0; ma < 4; ma++)
                    ldsm4(a[ma][0], a[ma][1], a[ma][2], a[ma][3], aT + ma * (16 * 144) + ks * 32);
                #pragma unroll
                for (int na = 0; na < 4; na++)
                    ldsm2(b[na][0], b[na][1], bT + na * (8 * 144) + ks * 32);
                #pragma unroll
                for (int ma = 0; ma < 4; ma++)
                    #pragma unroll
                    for (int na = 0; na < 4; na++) {
                        int* c = &acc[ma * 16 + na * 4];
                        imma(c[0], c[1], c[2], c[3],
                             a[ma][0], a[ma][1], a[ma][2], a[ma][3], b[na][0], b[na][1]);
                    }
            }
        } else {
            const int* Abuf = sdyn + buf * BUFI;
            const int* Bbuf = sdyn + BS_OFF + buf * BUFI;
            #pragma unroll
            for (int kwg = 0; kwg < 8; kwg++) {
                int4 b4[8];
                #pragma unroll
                for (int j = 0; j < 8; j++)
                    b4[j] = *(const int4*)&Bbuf[(64 + tx + 8 * j) * TPAD + kwg * 4];
                #pragma unroll
                for (int i = 0; i < 8; i++) {
                    int4 a4 = *(const int4*)&Abuf[(ry + 16 * i) * TPAD + kwg * 4];
                    #pragma unroll
                    for (int j = 0; j < 8; j++) {
                        int v = acc[i * 8 + j];
                        v = __dp4a(a4.x, b4[j].x, v);
                        v = __dp4a(a4.y, b4[j].y, v);
                        v = __dp4a(a4.z, b4[j].z, v);
                        v = __dp4a(a4.w, b4[j].w, v);
                        acc[i * 8 + j] = v;
                    }
                }
            }
        }
    }
    #undef FC_ISSUE
}

// ---------------- launch 4: fc1 -> relu+requant int8 X5 ----------------
__global__ void __launch_bounds__(256, 2) k_fc1(const float* __restrict__ sfs) {
    extern __shared__ int sdyn[];
    const int m0 = blockIdx.y * 128, h0 = blockIdx.x * 128;
    int acc[64];
    hybrid_mainloop((const char*)g_X4, (const char*)g_f1w8, 768, 6, m0, h0, sdyn, acc);

    const float r5 = __fdiv_rn(__fmul_rn(sfs[4], wsf_of(4)), sfs[5]);
    const int lane = threadIdx.x & 31, wid = threadIdx.x >> 5;
    if (wid < 4) {
        const int warp_m = (wid & 1) * 64, warp_n = (wid >> 1) * 32;
        #pragma unroll
        for (int ma = 0; ma < 4; ma++) {
            int row0 = m0 + warp_m + ma * 16 + (lane >> 2);
            #pragma unroll
            for (int na = 0; na < 4; na++) {
                int col0 = h0 + warp_n + na * 8 + (lane & 3) * 2;
                int bias0 = g_f1b[col0], bias1 = g_f1b[col0 + 1];
                #pragma unroll
                for (int h = 0; h < 2; h++) {
                    int row = row0 + h * 8;
                    int t0 = acc[ma * 16 + na * 4 + h * 2 + 0] + bias0; t0 = t0 > 0 ? t0 : 0;
                    int t1 = acc[ma * 16 + na * 4 + h * 2 + 1] + bias1; t1 = t1 > 0 ? t1 : 0;
                    int q0 = min(127, rni(__fmul_rn((float)t0, r5)));
                    int q1 = min(127, rni(__fmul_rn((float)t1, r5)));
                    *(short*)&g_X5[(long long)row * cH + col0] = (short)((q0 & 0xff) | (q1 << 8));
                }
            }
        }
    } else {
        const int ry = (threadIdx.x & 127) >> 3, tx = threadIdx.x & 7;
        int bias[8];
        #pragma unroll
        for (int j = 0; j < 8; j++) bias[j] = g_f1b[h0 + 64 + tx + 8 * j];
        #pragma unroll
        for (int i = 0; i < 8; i++) {
            long long rowb = (long long)(m0 + ry + 16 * i) * cH + h0 + 64 + tx;
            #pragma unroll
            for (int j = 0; j < 8; j++) {
                int t = acc[i * 8 + j] + bias[j]; t = t > 0 ? t : 0;
                g_X5[rowb + 8 * j] = (signed char)min(127, rni(__fmul_rn((float)t, r5)));
            }
        }
    }
}

// ---------------- launch 5: fc2 + gamma2 + residual + dequant -> fp32 out ----------------
__global__ void __launch_bounds__(256, 2) k_fc2(float* __restrict__ out,
                                                const float* __restrict__ sfs) {
    extern __shared__ int sdyn[];
    const int m0 = blockIdx.y * 128, h0 = blockIdx.x * 128;
    int acc[64];
    hybrid_mainloop((const char*)g_X5, (const char*)g_f2w8, 3072, 24, m0, h0, sdyn, acc);

    const float sf3 = sfs[3], sf5 = sfs[5], sf6 = sfs[6], sf7 = sfs[7];
    const float r6 = __fdiv_rn(__fmul_rn(sf5, wsf_of(5)), sf6);
    const float r7 = __fdiv_rn(__fmul_rn(sf6, wsf_of(6)), sf7);
    const float rid2 = __fdiv_rn(sf3, sf7);
    const int lane = threadIdx.x & 31, wid = threadIdx.x >> 5;
    if (wid < 4) {
        const int warp_m = (wid & 1) * 64, warp_n = (wid >> 1) * 32;
        #pragma unroll
        for (int ma = 0; ma < 4; ma++) {
            int row0 = m0 + warp_m + ma * 16 + (lane >> 2);
            #pragma unroll
            for (int na = 0; na < 4; na++) {
                int col0 = h0 + warp_n + na * 8 + (lane & 3) * 2;
                int bias0 = g_f2b[col0], bias1 = g_f2b[col0 + 1];
                int gw0 = g_g2wi[col0],  gw1 = g_g2wi[col0 + 1];
                #pragma unroll
                for (int h = 0; h < 2; h++) {
                    long long base = (long long)(row0 + h * 8) * cD + col0;
                    int x60 = clamp8(rni(__fmul_rn((float)(acc[ma * 16 + na * 4 + h * 2 + 0] + bias0), r6)));
                    int x61 = clamp8(rni(__fmul_rn((float)(acc[ma * 16 + na * 4 + h * 2 + 1] + bias1), r6)));
                    short xs = *(const short*)&g_X3[base];
                    int x3a = (signed char)(xs & 0xff);
                    int x3b = (int)(xs >> 8);
                    int v0 = clamp8(rni(__fmul_rn((float)(x60 * gw0), r7)) + rni(__fmul_rn((float)x3a, rid2)));
                    int v1 = clamp8(rni(__fmul_rn((float)(x61 * gw1), r7)) + rni(__fmul_rn((float)x3b, rid2)));
                    float2 o;
                    o.x = __fmul_rn((float)v0, sf7);
                    o.y = __fmul_rn((float)v1, sf7);
                    *(float2*)(out + base) = o;
                }
            }
        }
    } else {
        const int ry = (threadIdx.x & 127) >> 3, tx = threadIdx.x & 7;
        int bias[8], gw[8];
        #pragma unroll
        for (int j = 0; j < 8; j++) {
            bias[j] = g_f2b[h0 + 64 + tx + 8 * j];
            gw[j]   = g_g2wi[h0 + 64 + tx + 8 * j];
        }
        #pragma unroll
        for (int i = 0; i < 8; i++) {
            long long rowb = (long long)(m0 + ry + 16 * i) * cD + h0 + 64 + tx;
            #pragma unroll
            for (int j = 0; j < 8; j++) {
                int x6 = clamp8(rni(__fmul_rn((float)(acc[i * 8 + j] + bias[j]), r6)));
                int gg = x6 * gw[j];
                int x3v = g_X3[rowb + 8 * j];
                int v = clamp8(rni(__fmul_rn((float)gg, r7)) + rni(__fmul_rn((float)x3v, rid2)));
                out[rowb + 8 * j] = __fmul_rn((float)v, sf7);
            }
        }
    }
}

__global__ void k_tail(float* out, long long start, long long total, const float* act_sfs) {
    long long i = start + (long long)blockIdx.x * 256 + threadIdx.x;
    if (i < total) out[i] = act_sfs[7];
}

extern "C" void kernel_launch(void* const* d_in, const int* in_sizes, int n_in,
                              void* d_out, int out_size) {
    const float* x   = (const float*)d_in[0];
    const float* n1w = (const float*)d_in[1];
    const float* n1b = (const float*)d_in[2];
    const float* aw  = (const float*)d_in[3];
    const float* ab  = (const float*)d_in[4];
    const float* g1  = (const float*)d_in[5];
    const float* n2w = (const float*)d_in[6];
    const float* n2b = (const float*)d_in[7];
    const float* f1w = (const float*)d_in[8];
    const float* f1b = (const float*)d_in[9];
    const float* f2w = (const float*)d_in[10];
    const float* f2b = (const float*)d_in[11];
    const float* g2  = (const float*)d_in[12];
    const float* sfs = (const float*)d_in[13];
    float* out = (float*)d_out;

    cudaFuncSetAttribute(k_fc1, cudaFuncAttributeMaxDynamicSharedMemorySize, FC_SMEM);
    cudaFuncSetAttribute(k_fc2, cudaFuncAttributeMaxDynamicSharedMemorySize, FC_SMEM);

    k_maxabs<<<585, 256>>>(n1w, aw, g1, n2w, f1w, f2w, g2);
    k_qwin<<<QW_BLOCKS + IN_BLOCKS, 256>>>(n1w, n1b, aw, ab, g1, n2w, n2b,
                                           f1w, f1b, f2w, f2b, g2, x, sfs);
    {
        dim3 g(4, cD / 64, cB);
        k_attn<<<g, 256>>>(sfs);
    }
    {
        dim3 g(cH / 128, cM / 128);
        k_fc1<<<g, 256, FC_SMEM>>>(sfs);
    }
    {
        dim3 g(cD / 128, cM / 128);
        k_fc2<<<g, 256, FC_SMEM>>>(out, sfs);
    }
    long long total = (long long)out_size;
    if (total > (long long)BNDTOT) {
        long long tail = total - BNDTOT;
        k_tail<<<(int)((tail + 255) / 256), 256>>>(out, BNDTOT, total, sfs);
    }
}

// round 17
// speedup vs baseline: 1.0689x; 1.0155x over previous
#include <cuda_runtime.h>
#include <cstdint>

constexpr int cB = 64, cN = 196, cD = 768, cH = 3072;
constexpr int cM = cB * cN;            // 12544
constexpr int BNDTOT = cB * cN * cD;   // 9633792
constexpr int HDTOT = cH * cD;         // 2359296

__device__ int g_maxbits[7];           // zero-init; atomicMax idempotent across graph replays

__device__ signed char g_X0[BNDTOT];
__device__ signed char g_X1t[BNDTOT];          // [B,D,N]
__device__ signed char g_X3[BNDTOT];
__device__ signed char g_X4[BNDTOT];
__device__ signed char g_X5[(long long)cM * cH];
__device__ signed char g_aw8[cN * cN];
__device__ int  g_ab32[cN];
__device__ signed char g_f1w8[HDTOT];
__device__ int  g_f1b[cH];
__device__ signed char g_f2w8[HDTOT];
__device__ int  g_f2b[cD];
__device__ int  g_g1wi[cD], g_n2wi[cD], g_b2i[cD], g_g2wi[cD];

__device__ __forceinline__ int clamp8(int v) { return max(-128, min(127, v)); }
__device__ __forceinline__ int rni(float f)  { return __float2int_rn(f); }
__device__ __forceinline__ float wsf_of(int slot) {
    return __fdiv_rn(__int_as_float(g_maxbits[slot]), 127.0f);
}

__device__ __forceinline__ uint32_t smem_u32(const void* p) {
    uint32_t a;
    asm("{ .reg .u64 t; cvta.to.shared.u64 t, %1; cvt.u32.u64 %0, t; }" : "=r"(a) : "l"(p));
    return a;
}

#define CP16(d, s) asm volatile("cp.async.cg.shared.global [%0], [%1], 16;" :: "r"(d), "l"(s))
#define CPCOMMIT() asm volatile("cp.async.commit_group;" ::: "memory")
#define CPWAIT(n)  asm volatile("cp.async.wait_group %0;" :: "n"(n) : "memory")

// ---------------- launch 1: maxabs reductions (float4) ----------------
__global__ void k_maxabs(const float* n1w, const float* aw, const float* g1,
                         const float* n2w, const float* f1, const float* f2, const float* g2) {
    int bid = blockIdx.x;
    const float* src; int slot, n, base;
    if (bid < 288)      { src = f1; slot = 4; n = HDTOT;   base = bid; }
    else if (bid < 576) { src = f2; slot = 5; n = HDTOT;   base = bid - 288; }
    else if (bid < 581) { src = aw; slot = 1; n = cN * cN; base = bid - 576; }
    else {
        base = 0; n = cD;
        int s = bid - 581;
        if (s == 0)      { src = n1w; slot = 0; }
        else if (s == 1) { src = g1;  slot = 2; }
        else if (s == 2) { src = n2w; slot = 3; }
        else             { src = g2;  slot = 6; }
    }
    int start4 = base * 2048;                 // in float4 units (8192 floats / 4)
    int end4 = min(n >> 2, start4 + 2048);
    float m = 0.f;
    for (int i = start4 + threadIdx.x; i < end4; i += 256) {
        float4 v = reinterpret_cast<const float4*>(src)[i];
        m = fmaxf(m, fmaxf(fmaxf(fabsf(v.x), fabsf(v.y)), fmaxf(fabsf(v.z), fabsf(v.w))));
    }
    #pragma unroll
    for (int o = 16; o; o >>= 1) m = fmaxf(m, __shfl_xor_sync(0xffffffffu, m, o));
    __shared__ float sm[8];
    if ((threadIdx.x & 31) == 0) sm[threadIdx.x >> 5] = m;
    __syncthreads();
    if (threadIdx.x == 0) {
        for (int i = 1; i < 8; i++) m = fmaxf(m, sm[i]);
        atomicMax(&g_maxbits[slot], __float_as_int(m));
    }
}

// ---------------- launch 2: fused quantw + input ----------------
constexpr int HD4 = HDTOT / 4;
constexpr int RESTQ = cN * cN + cN + cH + cD + 4 * cD;
constexpr int TOTQ = 2 * HD4 + RESTQ;
constexpr int QW_BLOCKS = (TOTQ + 255) / 256;
constexpr int IN_BLOCKS = 12 * 4 * cB;   // 3072

__global__ void k_qwin(const float* n1w, const float* n1b, const float* aw, const float* ab,
                       const float* g1, const float* n2w, const float* n2b,
                       const float* f1w, const float* f1b, const float* f2w, const float* f2b,
                       const float* g2, const float* __restrict__ x,
                       const float* __restrict__ sfs) {
    __shared__ signed char s[64][68];
    __shared__ int swv[64], sbv[64];
    if (blockIdx.x < QW_BLOCKS) {
        const float w1 = wsf_of(1), w2 = wsf_of(2), w3 = wsf_of(3);
        const float w4 = wsf_of(4), w5 = wsf_of(5), w6 = wsf_of(6);
        const float sf1 = sfs[1], sf3 = sfs[3], sf4 = sfs[4], sf5 = sfs[5];
        const float den_ab  = __fmul_rn(sf1, w1);
        const float den_b2  = __fmul_rn(sf3, w3);
        const float den_f1b = __fmul_rn(sf4, w4);
        const float den_f2b = __fmul_rn(sf5, w5);

        int idx = blockIdx.x * 256 + threadIdx.x;
        if (idx < HD4) {
            float4 v = reinterpret_cast<const float4*>(f1w)[idx];
            char4 o;
            o.x = (signed char)clamp8(rni(__fdiv_rn(v.x, w4)));
            o.y = (signed char)clamp8(rni(__fdiv_rn(v.y, w4)));
            o.z = (signed char)clamp8(rni(__fdiv_rn(v.z, w4)));
            o.w = (signed char)clamp8(rni(__fdiv_rn(v.w, w4)));
            reinterpret_cast<char4*>(g_f1w8)[idx] = o;
            return;
        }
        idx -= HD4;
        if (idx < HD4) {
            float4 v = reinterpret_cast<const float4*>(f2w)[idx];
            char4 o;
            o.x = (signed char)clamp8(rni(__fdiv_rn(v.x, w5)));
            o.y = (signed char)clamp8(rni(__fdiv_rn(v.y, w5)));
            o.z = (signed char)clamp8(rni(__fdiv_rn(v.z, w5)));
            o.w = (signed char)clamp8(rni(__fdiv_rn(v.w, w5)));
            reinterpret_cast<char4*>(g_f2w8)[idx] = o;
            return;
        }
        idx -= HD4;
        if (idx < cN * cN) { g_aw8[idx] = (signed char)clamp8(rni(__fdiv_rn(aw[idx], w1))); return; }
        idx -= cN * cN;
        if (idx < cN) { g_ab32[idx] = rni(__fdiv_rn(ab[idx], den_ab)); return; }
        idx -= cN;
        if (idx < cH) { g_f1b[idx] = rni(__fdiv_rn(f1b[idx], den_f1b)); return; }
        idx -= cH;
        if (idx < cD) { g_f2b[idx] = rni(__fdiv_rn(f2b[idx], den_f2b)); return; }
        idx -= cD;
        if (idx < cD) { g_g1wi[idx] = rni(__fdiv_rn(g1[idx],  w2)); return; }
        idx -= cD;
        if (idx < cD) { g_n2wi[idx] = rni(__fdiv_rn(n2w[idx], w3)); return; }
        idx -= cD;
        if (idx < cD) { g_b2i[idx]  = rni(__fdiv_rn(n2b[idx], den_b2)); return; }
        idx -= cD;
        if (idx < cD) { g_g2wi[idx] = rni(__fdiv_rn(g2[idx],  w6)); return; }
        return;
    }
    // ---- input branch ----
    const float w0 = wsf_of(0);
    const float s0 = sfs[0];
    const float den_b1 = __fmul_rn(s0, w0);
    const float r1 = __fdiv_rn(den_b1, sfs[1]);
    int v = blockIdx.x - QW_BLOCKS;
    const int dt = v % 12, nt = (v / 12) % 4, b = v / 48;
    const int n0 = nt * 64, d0 = dt * 64;
    if (threadIdx.x < 64) {
        swv[threadIdx.x] = rni(__fdiv_rn(n1w[d0 + threadIdx.x], w0));
        sbv[threadIdx.x] = rni(__fdiv_rn(n1b[d0 + threadIdx.x], den_b1));
    }
    __syncthreads();
    const float* xb = x + (size_t)b * cN * cD;
    signed char* x0b = g_X0 + (size_t)b * cN * cD;
    #pragma unroll
    for (int it = 0; it < 4; it++) {
        int e = threadIdx.x + it * 256;
        int nl = e >> 4, gl = e & 15;
        int n = n0 + nl, d = d0 + gl * 4;
        if (n < cN) {
            float4 xv = *(const float4*)&xb[n * cD + d];
            int4 wv = *(const int4*)&swv[gl * 4];
            int4 bv = *(const int4*)&sbv[gl * 4];
            int xa = rni(__fdiv_rn(xv.x, s0));
            int xbq = rni(__fdiv_rn(xv.y, s0));
            int xc = rni(__fdiv_rn(xv.z, s0));
            int xd = rni(__fdiv_rn(xv.w, s0));
            char4 c0;
            c0.x = (signed char)xa; c0.y = (signed char)xbq;
            c0.z = (signed char)xc; c0.w = (signed char)xd;
            *(char4*)&x0b[n * cD + d] = c0;
            s[nl][gl * 4 + 0] = (signed char)clamp8(rni(__fmul_rn((float)(xa  * wv.x + bv.x), r1)));
            s[nl][gl * 4 + 1] = (signed char)clamp8(rni(__fmul_rn((float)(xbq * wv.y + bv.y), r1)));
            s[nl][gl * 4 + 2] = (signed char)clamp8(rni(__fmul_rn((float)(xc  * wv.z + bv.z), r1)));
            s[nl][gl * 4 + 3] = (signed char)clamp8(rni(__fmul_rn((float)(xd  * wv.w + bv.w), r1)));
        }
    }
    __syncthreads();
    const int nvalid = min(64, cN - n0);
    const int q4 = nvalid >> 2;
    for (int e = threadIdx.x; e < 64 * q4; e += 256) {
        int dl = e / q4, q = e - dl * q4;
        int nq = q * 4;
        char4 c;
        c.x = s[nq + 0][dl];
        c.y = s[nq + 1][dl];
        c.z = s[nq + 2][dl];
        c.w = s[nq + 3][dl];
        *(char4*)&g_X1t[((size_t)b * cD + d0 + dl) * cN + n0 + nq] = c;
    }
}

// ---------------- launch 3: attn GEMM + gamma1 + residual + norm2 (1x2 d-tiling) ----------------
__global__ void __launch_bounds__(256) k_attn(const float* __restrict__ sfs) {
    __shared__ int sx[64][52];
    __shared__ int sw[49][52];
    const float sf0 = sfs[0], sf1 = sfs[1], sf2 = sfs[2], sf3 = sfs[3], sf4 = sfs[4];
    const float r2 = __fdiv_rn(__fmul_rn(sf1, wsf_of(1)), sf2);
    const float r3 = __fdiv_rn(__fmul_rn(sf2, wsf_of(2)), sf3);
    const float rid1 = __fdiv_rn(sf0, sf3);
    const float r4 = __fdiv_rn(__fmul_rn(sf3, wsf_of(3)), sf4);

    const int b = blockIdx.z, d0 = blockIdx.y * 64, o0 = blockIdx.x * 49;
    const int* X1ti = (const int*)g_X1t;
    for (int i = threadIdx.x; i < 64 * 49; i += 256) {
        int r = i / 49, c2 = i % 49;
        sx[r][c2] = X1ti[((size_t)b * cD + d0 + r) * 49 + c2];
    }
    const int* awi = (const int*)g_aw8;
    for (int i = threadIdx.x; i < 49 * 49; i += 256) {
        int r = i / 49, c2 = i % 49;
        sw[r][c2] = awi[(o0 + r) * 49 + c2];
    }
    __syncthreads();
    for (int j = threadIdx.x; j < 49 * 32; j += 256) {
        int dl = j & 31, o = j >> 5;
        int ab0 = g_ab32[o0 + o];
        int acc0 = ab0, acc1 = ab0;
        #pragma unroll
        for (int w4 = 0; w4 < 12; w4++) {
            int4 wa  = *(const int4*)&sw[o][w4 * 4];
            int4 xa0 = *(const int4*)&sx[dl][w4 * 4];
            int4 xa1 = *(const int4*)&sx[dl + 32][w4 * 4];
            acc0 = __dp4a(xa0.x, wa.x, acc0);
            acc0 = __dp4a(xa0.y, wa.y, acc0);
            acc0 = __dp4a(xa0.z, wa.z, acc0);
            acc0 = __dp4a(xa0.w, wa.w, acc0);
            acc1 = __dp4a(xa1.x, wa.x, acc1);
            acc1 = __dp4a(xa1.y, wa.y, acc1);
            acc1 = __dp4a(xa1.z, wa.z, acc1);
            acc1 = __dp4a(xa1.w, wa.w, acc1);
        }
        {
            int wlast = sw[o][48];
            acc0 = __dp4a(sx[dl][48], wlast, acc0);
            acc1 = __dp4a(sx[dl + 32][48], wlast, acc1);
        }
        const size_t gibase = (size_t)b * cN * cD + (size_t)(o0 + o) * cD;
        const int dg0 = d0 + dl;
        int g1a = g_g1wi[dg0], g1b = g_g1wi[dg0 + 32];
        int n2a = g_n2wi[dg0], n2b_ = g_n2wi[dg0 + 32];
        int b2a = g_b2i[dg0],  b2b = g_b2i[dg0 + 32];
        #pragma unroll
        for (int h = 0; h < 2; h++) {
            int acc = h ? acc1 : acc0;
            int dg = dg0 + h * 32;
            int x2 = clamp8(rni(__fmul_rn((float)acc, r2)));
            int gg = x2 * (h ? g1b : g1a);
            size_t gi = gibase + dg;
            int x0v = g_X0[gi];
            int x3 = clamp8(rni(__fmul_rn((float)gg, r3)) + rni(__fmul_rn((float)x0v, rid1)));
            g_X3[gi] = (signed char)x3;
            int z4 = x3 * (h ? n2b_ : n2a) + (h ? b2b : b2a);
            g_X4[gi] = (signed char)clamp8(rni(__fmul_rn((float)z4, r4)));
        }
    }
}

// ---------------- hybrid tensor(IMMA 64 cols) + dp4a (64 cols), cp.async 3-stage ----------------
__device__ __forceinline__ void imma(int& c0, int& c1, int& c2, int& c3,
                                     int a0, int a1, int a2, int a3, int b0, int b1) {
    asm volatile(
        "mma.sync.aligned.m16n8k32.row.col.s32.s8.s8.s32 "
        "{%0,%1,%2,%3}, {%4,%5,%6,%7}, {%8,%9}, {%0,%1,%2,%3};"
        : "+r"(c0), "+r"(c1), "+r"(c2), "+r"(c3)
        : "r"(a0), "r"(a1), "r"(a2), "r"(a3), "r"(b0), "r"(b1));
}
__device__ __forceinline__ void ldsm4(int& r0, int& r1, int& r2, int& r3, uint32_t a) {
    asm volatile("ldmatrix.sync.aligned.m8n8.x4.shared.b16 {%0,%1,%2,%3}, [%4];"
                 : "=r"(r0), "=r"(r1), "=r"(r2), "=r"(r3) : "r"(a));
}
__device__ __forceinline__ void ldsm2(int& r0, int& r1, uint32_t a) {
    asm volatile("ldmatrix.sync.aligned.m8n8.x2.shared.b16 {%0,%1}, [%2];"
                 : "=r"(r0), "=r"(r1) : "r"(a));
}

constexpr int TPAD = 36;
constexpr int BUFI = 128 * TPAD;       // 4608 ints
constexpr int BS_OFF = 3 * BUFI;       // 13824 ints
constexpr int FC_SMEM = 2 * 3 * BUFI * 4;  // 110592 bytes

__device__ __forceinline__ void hybrid_mainloop(
    const char* __restrict__ A, const char* __restrict__ B, int ldb /*bytes*/, int KI,
    int m0, int n0, int* sdyn, int acc[64])
{
    const int tid = threadIdx.x;
    const int lane = tid & 31, wid = tid >> 5;
    const int SEG = tid & 7, RG = tid >> 3;
    const uint32_t sbase = smem_u32(sdyn);
    const uint32_t asB = sbase, bsB = sbase + BS_OFF * 4;

    const int warp_m = (wid & 1) * 64, warp_n = (wid >> 1) * 32;
    const int arow_l = warp_m + (lane & 7) + ((lane >> 3) & 1) * 8;
    const uint32_t aAddr = asB + (uint32_t)arow_l * 144 + (lane >> 4) * 16;
    const int brow_l = warp_n + (lane & 7);
    const uint32_t bAddr = bsB + (uint32_t)brow_l * 144 + ((lane >> 3) & 1) * 16;
    const int ry = (tid & 127) >> 3, tx = tid & 7;

    #pragma unroll
    for (int i = 0; i < 64; i++) acc[i] = 0;

    const char* aSrc = A + (long long)(m0 + RG) * ldb + SEG * 16;
    const char* bSrc = B + (long long)(n0 + RG) * ldb + SEG * 16;
    const uint32_t aDst = asB + (uint32_t)RG * 144 + SEG * 16;
    const uint32_t bDst = bsB + (uint32_t)RG * 144 + SEG * 16;

    #define FC_ISSUE(kc) do {                                                     \
        int _buf = (kc) % 3;                                                      \
        uint32_t _ad = aDst + _buf * (BUFI * 4);                                  \
        uint32_t _bd = bDst + _buf * (BUFI * 4);                                  \
        const char* _as = aSrc + (kc) * 128;                                      \
        const char* _bs = bSrc + (kc) * 128;                                      \
        _Pragma("unroll")                                                         \
        for (int _p = 0; _p < 4; _p++) {                                          \
            CP16(_ad + _p * (32 * 144), _as + (long long)(32 * _p) * ldb);        \
            CP16(_bd + _p * (32 * 144), _bs + (long long)(32 * _p) * ldb);        \
        }                                                                         \
        CPCOMMIT();                                                               \
    } while (0)

    FC_ISSUE(0);
    if (KI > 1) FC_ISSUE(1);

    for (int kc = 0; kc < KI; kc++) {
        if (kc + 1 < KI) { CPWAIT(1); } else { CPWAIT(0); }
        __syncthreads();
        if (kc + 2 < KI) FC_ISSUE(kc + 2);
        const int buf = kc % 3;
        if (wid < 4) {
            const uint32_t aT = aAddr + buf * (BUFI * 4);
            const uint32_t bT = bAddr + buf * (BUFI * 4);
            #pragma unroll
            for (int ks = 0; ks < 4; ks++) {
                int a[4][4], b[4][2];
                #pragma unroll
                for (int ma = 0; ma < 4; ma++)
                    ldsm4(a[ma][0], a[ma][1], a[ma][2], a[ma][3], aT + ma * (16 * 144) + ks * 32);
                #pragma unroll
                for (int na = 0; na < 4; na++)
                    ldsm2(b[na][0], b[na][1], bT + na * (8 * 144) + ks * 32);
                #pragma unroll
                for (int ma = 0; ma < 4; ma++)
                    #pragma unroll
                    for (int na = 0; na < 4; na++) {
                        int* c = &acc[ma * 16 + na * 4];
                        imma(c[0], c[1], c[2], c[3],
                             a[ma][0], a[ma][1], a[ma][2], a[ma][3], b[na][0], b[na][1]);
                    }
            }
        } else {
            const int* Abuf = sdyn + buf * BUFI;
            const int* Bbuf = sdyn + BS_OFF + buf * BUFI;
            #pragma unroll
            for (int kwg = 0; kwg < 8; kwg++) {
                int4 b4[8];
                #pragma unroll
                for (int j = 0; j < 8; j++)
                    b4[j] = *(const int4*)&Bbuf[(64 + tx + 8 * j) * TPAD + kwg * 4];
                #pragma unroll
                for (int i = 0; i < 8; i++) {
                    int4 a4 = *(const int4*)&Abuf[(ry + 16 * i) * TPAD + kwg * 4];
                    #pragma unroll
                    for (int j = 0; j < 8; j++) {
                        int v = acc[i * 8 + j];
                        v = __dp4a(a4.x, b4[j].x, v);
                        v = __dp4a(a4.y, b4[j].y, v);
                        v = __dp4a(a4.z, b4[j].z, v);
                        v = __dp4a(a4.w, b4[j].w, v);
                        acc[i * 8 + j] = v;
                    }
                }
            }
        }
    }
    #undef FC_ISSUE
}

// ---------------- launch 4: fc1 -> relu+requant int8 X5 ----------------
__global__ void __launch_bounds__(256, 2) k_fc1(const float* __restrict__ sfs) {
    extern __shared__ int sdyn[];
    const int m0 = blockIdx.y * 128, h0 = blockIdx.x * 128;
    int acc[64];
    hybrid_mainloop((const char*)g_X4, (const char*)g_f1w8, 768, 6, m0, h0, sdyn, acc);

    const float r5 = __fdiv_rn(__fmul_rn(sfs[4], wsf_of(4)), sfs[5]);
    const int lane = threadIdx.x & 31, wid = threadIdx.x >> 5;
    if (wid < 4) {
        const int warp_m = (wid & 1) * 64, warp_n = (wid >> 1) * 32;
        #pragma unroll
        for (int ma = 0; ma < 4; ma++) {
            int row0 = m0 + warp_m + ma * 16 + (lane >> 2);
            #pragma unroll
            for (int na = 0; na < 4; na++) {
                int col0 = h0 + warp_n + na * 8 + (lane & 3) * 2;
                int bias0 = g_f1b[col0], bias1 = g_f1b[col0 + 1];
                #pragma unroll
                for (int h = 0; h < 2; h++) {
                    int row = row0 + h * 8;
                    int t0 = acc[ma * 16 + na * 4 + h * 2 + 0] + bias0; t0 = t0 > 0 ? t0 : 0;
                    int t1 = acc[ma * 16 + na * 4 + h * 2 + 1] + bias1; t1 = t1 > 0 ? t1 : 0;
                    int q0 = min(127, rni(__fmul_rn((float)t0, r5)));
                    int q1 = min(127, rni(__fmul_rn((float)t1, r5)));
                    *(short*)&g_X5[(long long)row * cH + col0] = (short)((q0 & 0xff) | (q1 << 8));
                }
            }
        }
    } else {
        const int ry = (threadIdx.x & 127) >> 3, tx = threadIdx.x & 7;
        int bias[8];
        #pragma unroll
        for (int j = 0; j < 8; j++) bias[j] = g_f1b[h0 + 64 + tx + 8 * j];
        #pragma unroll
        for (int i = 0; i < 8; i++) {
            long long rowb = (long long)(m0 + ry + 16 * i) * cH + h0 + 64 + tx;
            #pragma unroll
            for (int j = 0; j < 8; j++) {
                int t = acc[i * 8 + j] + bias[j]; t = t > 0 ? t : 0;
                g_X5[rowb + 8 * j] = (signed char)min(127, rni(__fmul_rn((float)t, r5)));
            }
        }
    }
}

// ---------------- launch 5: fc2 + gamma2 + residual + dequant -> fp32 out ----------------
__global__ void __launch_bounds__(256, 2) k_fc2(float* __restrict__ out,
                                                const float* __restrict__ sfs) {
    extern __shared__ int sdyn[];
    const int m0 = blockIdx.y * 128, h0 = blockIdx.x * 128;
    int acc[64];
    hybrid_mainloop((const char*)g_X5, (const char*)g_f2w8, 3072, 24, m0, h0, sdyn, acc);

    const float sf3 = sfs[3], sf5 = sfs[5], sf6 = sfs[6], sf7 = sfs[7];
    const float r6 = __fdiv_rn(__fmul_rn(sf5, wsf_of(5)), sf6);
    const float r7 = __fdiv_rn(__fmul_rn(sf6, wsf_of(6)), sf7);
    const float rid2 = __fdiv_rn(sf3, sf7);
    const int lane = threadIdx.x & 31, wid = threadIdx.x >> 5;
    if (wid < 4) {
        const int warp_m = (wid & 1) * 64, warp_n = (wid >> 1) * 32;
        #pragma unroll
        for (int ma = 0; ma < 4; ma++) {
            int row0 = m0 + warp_m + ma * 16 + (lane >> 2);
            #pragma unroll
            for (int na = 0; na < 4; na++) {
                int col0 = h0 + warp_n + na * 8 + (lane & 3) * 2;
                int bias0 = g_f2b[col0], bias1 = g_f2b[col0 + 1];
                int gw0 = g_g2wi[col0],  gw1 = g_g2wi[col0 + 1];
                #pragma unroll
                for (int h = 0; h < 2; h++) {
                    long long base = (long long)(row0 + h * 8) * cD + col0;
                    int x60 = clamp8(rni(__fmul_rn((float)(acc[ma * 16 + na * 4 + h * 2 + 0] + bias0), r6)));
                    int x61 = clamp8(rni(__fmul_rn((float)(acc[ma * 16 + na * 4 + h * 2 + 1] + bias1), r6)));
                    short xs = *(const short*)&g_X3[base];
                    int x3a = (signed char)(xs & 0xff);
                    int x3b = (int)(xs >> 8);
                    int v0 = clamp8(rni(__fmul_rn((float)(x60 * gw0), r7)) + rni(__fmul_rn((float)x3a, rid2)));
                    int v1 = clamp8(rni(__fmul_rn((float)(x61 * gw1), r7)) + rni(__fmul_rn((float)x3b, rid2)));
                    float2 o;
                    o.x = __fmul_rn((float)v0, sf7);
                    o.y = __fmul_rn((float)v1, sf7);
                    *(float2*)(out + base) = o;
                }
            }
        }
    } else {
        const int ry = (threadIdx.x & 127) >> 3, tx = threadIdx.x & 7;
        int bias[8], gw[8];
        #pragma unroll
        for (int j = 0; j < 8; j++) {
            bias[j] = g_f2b[h0 + 64 + tx + 8 * j];
            gw[j]   = g_g2wi[h0 + 64 + tx + 8 * j];
        }
        #pragma unroll
        for (int i = 0; i < 8; i++) {
            long long rowb = (long long)(m0 + ry + 16 * i) * cD + h0 + 64 + tx;
            #pragma unroll
            for (int j = 0; j < 8; j++) {
                int x6 = clamp8(rni(__fmul_rn((float)(acc[i * 8 + j] + bias[j]), r6)));
                int gg = x6 * gw[j];
                int x3v = g_X3[rowb + 8 * j];
                int v = clamp8(rni(__fmul_rn((float)gg, r7)) + rni(__fmul_rn((float)x3v, rid2)));
                out[rowb + 8 * j] = __fmul_rn((float)v, sf7);
            }
        }
    }
}

__global__ void k_tail(float* out, long long start, long long total, const float* act_sfs) {
    long long i = start + (long long)blockIdx.x * 256 + threadIdx.x;
    if (i < total) out[i] = act_sfs[7];
}

extern "C" void kernel_launch(void* const* d_in, const int* in_sizes, int n_in,
                              void* d_out, int out_size) {
    const float* x   = (const float*)d_in[0];
    const float* n1w = (const float*)d_in[1];
    const float* n1b = (const float*)d_in[2];
    const float* aw  = (const float*)d_in[3];
    const float* ab  = (const float*)d_in[4];
    const float* g1  = (const float*)d_in[5];
    const float* n2w = (const float*)d_in[6];
    const float* n2b = (const float*)d_in[7];
    const float* f1w = (const float*)d_in[8];
    const float* f1b = (const float*)d_in[9];
    const float* f2w = (const float*)d_in[10];
    const float* f2b = (const float*)d_in[11];
    const float* g2  = (const float*)d_in[12];
    const float* sfs = (const float*)d_in[13];
    float* out = (float*)d_out;

    cudaFuncSetAttribute(k_fc1, cudaFuncAttributeMaxDynamicSharedMemorySize, FC_SMEM);
    cudaFuncSetAttribute(k_fc2, cudaFuncAttributeMaxDynamicSharedMemorySize, FC_SMEM);

    k_maxabs<<<585, 256>>>(n1w, aw, g1, n2w, f1w, f2w, g2);
    k_qwin<<<QW_BLOCKS + IN_BLOCKS, 256>>>(n1w, n1b, aw, ab, g1, n2w, n2b,
                                           f1w, f1b, f2w, f2b, g2, x, sfs);
    {
        dim3 g(4, cD / 64, cB);
        k_attn<<<g, 256>>>(sfs);
    }
    {
        dim3 g(cH / 128, cM / 128);
        k_fc1<<<g, 256, FC_SMEM>>>(sfs);
    }
    {
        dim3 g(cD / 128, cM / 128);
        k_fc2<<<g, 256, FC_SMEM>>>(out, sfs);
    }
    long long total = (long long)out_size;
    if (total > (long long)BNDTOT) {
        long long tail = total - BNDTOT;
        k_tail<<<(int)((tail + 255) / 256), 256>>>(out, BNDTOT, total, sfs);
    }
}